// round 2
// baseline (speedup 1.0000x reference)
#include <cuda_runtime.h>

#define BB   8
#define ATOT 196416
#define KTOT 4576
#define BXC  4.135166556742356f   /* log(1000/16) */
#define ROWW 16

__constant__ int c_ln[5]    = {147456,36864,9216,2304,576};
__constant__ int c_loff[5]  = {0,147456,184320,193536,195840};
__constant__ int c_lk[5]    = {1000,1000,1000,1000,576};
__constant__ int c_lkoff[5] = {0,1000,2000,3000,4000};

__device__ int    g_selidx[BB*KTOT];
__device__ float4 g_boxes [BB*KTOT];
__device__ float  g_scores[BB*KTOT];
__device__ int    g_valid [BB*KTOT];
__device__ int    g_keep  [BB*KTOT];
__device__ int    g_maxb  [BB];

__device__ __forceinline__ unsigned fkey(float f){
    unsigned u = __float_as_uint(f);
    return (u & 0x80000000u) ? ~u : (u | 0x80000000u);
}

__device__ void bitonic_desc_u64(unsigned long long* a, int n){
    for (int k = 2; k <= n; k <<= 1)
        for (int j = k >> 1; j > 0; j >>= 1){
            for (int idx = threadIdx.x; idx < n; idx += blockDim.x){
                int ixj = idx ^ j;
                if (ixj > idx){
                    unsigned long long x = a[idx], y = a[ixj];
                    bool sw = ((idx & k) == 0) ? (x < y) : (x > y);
                    if (sw){ a[idx] = y; a[ixj] = x; }
                }
            }
            __syncthreads();
        }
}
__device__ void bitonic_asc_u32(unsigned* a, int n){
    for (int k = 2; k <= n; k <<= 1)
        for (int j = k >> 1; j > 0; j >>= 1){
            for (int idx = threadIdx.x; idx < n; idx += blockDim.x){
                int ixj = idx ^ j;
                if (ixj > idx){
                    unsigned x = a[idx], y = a[ixj];
                    bool sw = ((idx & k) == 0) ? (x > y) : (x < y);
                    if (sw){ a[idx] = y; a[ixj] = x; }
                }
            }
            __syncthreads();
        }
}

/* ---------------- K1: exact per-(batch,level) top-k via 3-pass radix select ---------------- */
__global__ __launch_bounds__(1024) void topk_kernel(const float* __restrict__ obj){
    __shared__ unsigned hist[2048];
    __shared__ unsigned long long sel[1024];
    __shared__ unsigned ties[1024];
    __shared__ int s_t, s_rem, s_ngt, s_neq;

    int lev = blockIdx.x, b = blockIdx.y, tid = threadIdx.x;
    if (lev == 0 && b == 0 && tid < BB) g_maxb[tid] = 0;  /* reset per launch */
    int n = c_ln[lev], k = c_lk[lev];
    const float* p = obj + (size_t)b*ATOT + c_loff[lev];
    int lane = tid & 31;

    /* pass 1: bins = key >> 21 */
    for (int i = tid; i < 2048; i += 1024) hist[i] = 0;
    __syncthreads();
    for (int base = 0; base < n; base += 1024){
        int i = base + tid;
        unsigned bin = 0xFFFFFFFFu;
        if (i < n) bin = fkey(p[i]) >> 21;
        unsigned mm = __match_any_sync(0xFFFFFFFFu, bin);
        if (bin != 0xFFFFFFFFu && lane == (__ffs(mm)-1)) atomicAdd(&hist[bin], __popc(mm));
    }
    __syncthreads();
    if (tid == 0){
        unsigned c = 0; int t = 2047;
        for (; t > 0; --t){ unsigned h = hist[t]; if (c + h >= (unsigned)k) break; c += h; }
        s_t = t; s_rem = k - (int)c;
    }
    __syncthreads();
    unsigned t1 = (unsigned)s_t; int k1 = s_rem;
    __syncthreads();

    /* pass 2: bins = (key>>10)&0x7FF among prefix==t1 */
    for (int i = tid; i < 2048; i += 1024) hist[i] = 0;
    __syncthreads();
    for (int base = 0; base < n; base += 1024){
        int i = base + tid;
        unsigned bin = 0xFFFFFFFFu;
        if (i < n){ unsigned u = fkey(p[i]); if ((u >> 21) == t1) bin = (u >> 10) & 0x7FFu; }
        unsigned mm = __match_any_sync(0xFFFFFFFFu, bin);
        if (bin != 0xFFFFFFFFu && lane == (__ffs(mm)-1)) atomicAdd(&hist[bin], __popc(mm));
    }
    __syncthreads();
    if (tid == 0){
        unsigned c = 0; int t = 2047;
        for (; t > 0; --t){ unsigned h = hist[t]; if (c + h >= (unsigned)k1) break; c += h; }
        s_t = t; s_rem = k1 - (int)c;
    }
    __syncthreads();
    unsigned t2 = (unsigned)s_t; int k2 = s_rem;
    __syncthreads();
    unsigned pre22 = (t1 << 11) | t2;

    /* pass 3: bins = key & 0x3FF among 22-bit prefix match */
    if (tid < 1024) hist[tid] = 0;
    __syncthreads();
    for (int base = 0; base < n; base += 1024){
        int i = base + tid;
        unsigned bin = 0xFFFFFFFFu;
        if (i < n){ unsigned u = fkey(p[i]); if ((u >> 10) == pre22) bin = u & 0x3FFu; }
        unsigned mm = __match_any_sync(0xFFFFFFFFu, bin);
        if (bin != 0xFFFFFFFFu && lane == (__ffs(mm)-1)) atomicAdd(&hist[bin], __popc(mm));
    }
    __syncthreads();
    if (tid == 0){
        unsigned c = 0; int t = 1023;
        for (; t > 0; --t){ unsigned h = hist[t]; if (c + h >= (unsigned)k2) break; c += h; }
        s_t = t; s_rem = k2 - (int)c;
        s_ngt = 0; s_neq = 0;
    }
    __syncthreads();
    unsigned T = (pre22 << 10) | (unsigned)s_t;
    int rem = s_rem;

    /* collect: strictly-above + ties at T */
    for (int i = tid; i < n; i += 1024){
        unsigned u = fkey(p[i]);
        if (u > T){
            int q = atomicAdd(&s_ngt, 1);
            sel[q] = ((unsigned long long)u << 32) | (unsigned long long)(0xFFFFFFFFu - (unsigned)i);
        } else if (u == T){
            int q = atomicAdd(&s_neq, 1);
            if (q < 1024) ties[q] = (unsigned)i;
        }
    }
    __syncthreads();
    int ngt = s_ngt, neq = min(s_neq, 1024);
    for (int i = neq + tid; i < 1024; i += 1024) ties[i] = 0xFFFFFFFFu;
    __syncthreads();
    bitonic_asc_u32(ties, 1024);           /* smallest indices first among ties */
    for (int r = tid; r < rem; r += 1024)
        sel[ngt + r] = ((unsigned long long)T << 32) | (unsigned long long)(0xFFFFFFFFu - ties[r]);
    for (int r = k + tid; r < 1024; r += 1024) sel[r] = 0ull;
    __syncthreads();
    bitonic_desc_u64(sel, 1024);           /* (value desc, idx asc) = lax.top_k order */
    int koff = c_lkoff[lev], off = c_loff[lev];
    for (int r = tid; r < k; r += 1024){
        unsigned li = 0xFFFFFFFFu - (unsigned)(sel[r] & 0xFFFFFFFFull);
        g_selidx[b*KTOT + koff + r] = off + (int)li;
    }
}

/* ---------------- K2: decode + clip + score + validity + per-image coord max ---------------- */
__global__ void decode_kernel(const float* __restrict__ obj,
                              const float* __restrict__ deltas,
                              const float* __restrict__ anchors){
    int e = blockIdx.x*blockDim.x + threadIdx.x;
    if (e >= BB*KTOT) return;
    int b = e / KTOT;
    int a = g_selidx[e];
    const float* an = anchors + 4*(size_t)a;
    float ax1 = an[0], ay1 = an[1], ax2 = an[2], ay2 = an[3];
    float wa = ax2 - ax1, ha = ay2 - ay1;
    float cxa = ax1 + 0.5f*wa, cya = ay1 + 0.5f*ha;
    const float* d = deltas + ((size_t)b*ATOT + a)*4;
    float dx = d[0], dy = d[1];
    float dw = fminf(d[2], BXC), dh = fminf(d[3], BXC);
    float pcx = dx*wa + cxa, pcy = dy*ha + cya;
    float pw = expf(dw)*wa, ph = expf(dh)*ha;
    float x1 = pcx - 0.5f*pw, y1 = pcy - 0.5f*ph;
    float x2 = pcx + 0.5f*pw, y2 = pcy + 0.5f*ph;
    x1 = fminf(fmaxf(x1, 0.f), 1024.f);
    y1 = fminf(fmaxf(y1, 0.f), 768.f);
    x2 = fminf(fmaxf(x2, 0.f), 1024.f);
    y2 = fminf(fmaxf(y2, 0.f), 768.f);
    float xo = obj[(size_t)b*ATOT + a];
    float s = 1.f/(1.f + expf(-xo));
    int v = ((x2 - x1) >= 1.0f) && ((y2 - y1) >= 1.0f) && (s >= 0.f);
    g_boxes[e]  = make_float4(x1, y1, x2, y2);
    g_scores[e] = s;
    g_valid[e]  = v;
    float mx = fmaxf(fmaxf(x1, y1), fmaxf(x2, y2));   /* all coords >= 0 -> int-compare safe */
    atomicMax(&g_maxb[b], __float_as_int(mx));
}

/* ---------------- K3: per-(batch,level) greedy NMS (level offsets -> separable) ------------- */
__global__ __launch_bounds__(512) void nms_kernel(){
    extern __shared__ unsigned char dsm_nms[];
    float* sx1 = (float*)dsm_nms;
    float* sy1 = sx1 + 1024;
    float* sx2 = sy1 + 1024;
    float* sy2 = sx2 + 1024;
    float* sar = sy2 + 1024;
    unsigned long long* mat = (unsigned long long*)(sar + 1024);  /* 1024 rows x 16 words */
    __shared__ unsigned long long keepw[ROWW];
    __shared__ unsigned slist[1024];
    __shared__ unsigned char vsm[1024];
    __shared__ int s_ns;

    int lev = blockIdx.x, b = blockIdx.y, tid = threadIdx.x;
    int m = c_lk[lev];
    int base = b*KTOT + c_lkoff[lev];
    float c = (float)lev * (__int_as_float(g_maxb[b]) + 1.0f);  /* batched_nms offset */
    if (tid == 0) s_ns = 0;
    for (int i = tid; i < m; i += blockDim.x){
        float4 bx = g_boxes[base + i];
        float nx1 = bx.x + c, ny1 = bx.y + c, nx2 = bx.z + c, ny2 = bx.w + c;
        sx1[i] = nx1; sy1[i] = ny1; sx2[i] = nx2; sy2[i] = ny2;
        sar[i] = (nx2 - nx1)*(ny2 - ny1);
        vsm[i] = (unsigned char)g_valid[base + i];
    }
    __syncthreads();
    if (tid < ROWW){
        unsigned long long kw = 0ull;
        int j0 = tid << 6;
        for (int t = 0; t < 64; ++t){
            int i = j0 + t;
            if (i < m && vsm[i]) kw |= (1ull << t);
        }
        keepw[tid] = kw;
    }
    /* phase A: suppression bit-matrix (only j > i bits) */
    for (int task = tid; task < m*ROWW; task += blockDim.x){
        int i = task >> 4, w = task & (ROWW-1);
        int j0 = w << 6;
        unsigned long long bits = 0ull;
        int jend = min(j0 + 64, m);
        int jstart = max(j0, i + 1);
        if (jstart < jend){
            float ax1 = sx1[i], ay1 = sy1[i], ax2 = sx2[i], ay2 = sy2[i], aa = sar[i];
            for (int j = jstart; j < jend; ++j){
                float iw = fmaxf(fminf(ax2, sx2[j]) - fmaxf(ax1, sx1[j]), 0.f);
                float ih = fmaxf(fminf(ay2, sy2[j]) - fmaxf(ay1, sy1[j]), 0.f);
                float inter = iw*ih;
                float iou = inter / fmaxf(aa + sar[j] - inter, 1e-9f);
                if (iou > 0.7f) bits |= (1ull << (j - j0));
            }
        }
        mat[i*ROWW + w] = bits;
    }
    __syncthreads();
    /* only rows that can suppress something need the serial pass */
    for (int i = tid; i < m; i += blockDim.x){
        unsigned long long any = 0ull;
        #pragma unroll
        for (int w = 0; w < ROWW; ++w) any |= mat[i*ROWW + w];
        if (any){ int p = atomicAdd(&s_ns, 1); slist[p] = (unsigned)i; }
    }
    __syncthreads();
    int ns = s_ns;
    for (int i = ns + tid; i < 1024; i += blockDim.x) slist[i] = 0xFFFFFFFFu;
    __syncthreads();
    bitonic_asc_u32(slist, 1024);
    /* phase B: serial greedy over suppressor rows only (warp 0) */
    if (tid < 32){
        for (int s = 0; s < ns; ++s){
            int i = (int)slist[s];
            unsigned long long kw = keepw[i >> 6];
            if ((kw >> (i & 63)) & 1ull){
                if (tid < ROWW) keepw[tid] &= ~mat[i*ROWW + tid];
            }
            __syncwarp();
        }
    }
    __syncthreads();
    for (int i = tid; i < m; i += blockDim.x)
        g_keep[base + i] = (int)((keepw[i >> 6] >> (i & 63)) & 1ull);
}

/* ---------------- K4: per-image post-NMS top-1000 (score desc, K-pos asc) + write ----------- */
__global__ __launch_bounds__(1024) void final_kernel(float* __restrict__ out){
    extern __shared__ unsigned long long arr_fin[];
    int b = blockIdx.x, tid = threadIdx.x;
    for (int i = tid; i < 8192; i += 1024){
        unsigned long long key = 0ull;
        if (i < KTOT && g_keep[b*KTOT + i]){
            unsigned mk = __float_as_uint(g_scores[b*KTOT + i]) | 0x80000000u; /* s >= 0 */
            key = ((unsigned long long)mk << 32) | (unsigned long long)(0xFFFFFFFFu - (unsigned)i);
        }
        arr_fin[i] = key;
    }
    __syncthreads();
    bitonic_desc_u64(arr_fin, 8192);
    for (int r = tid; r < 1000; r += 1024){
        unsigned long long cc = arr_fin[r];
        float* o = out + ((size_t)b*1000 + r)*5;
        if (cc){
            int pos = (int)(0xFFFFFFFFu - (unsigned)(cc & 0xFFFFFFFFull));
            float4 bx = g_boxes[b*KTOT + pos];
            o[0] = bx.x; o[1] = bx.y; o[2] = bx.z; o[3] = bx.w;
            o[4] = g_scores[b*KTOT + pos];
        } else {
            o[0] = 0.f; o[1] = 0.f; o[2] = 0.f; o[3] = 0.f; o[4] = 0.f;
        }
    }
}

extern "C" void kernel_launch(void* const* d_in, const int* in_sizes, int n_in,
                              void* d_out, int out_size){
    const float* obj     = (const float*)d_in[0];
    const float* deltas  = (const float*)d_in[1];
    const float* anchors = (const float*)d_in[2];
    float* out = (float*)d_out;

    const int DSM_NMS = 5*1024*4 + 1024*ROWW*8;   /* 151552 */
    const int DSM_FIN = 8192*8;                    /* 65536  */
    cudaFuncSetAttribute(nms_kernel,   cudaFuncAttributeMaxDynamicSharedMemorySize, DSM_NMS);
    cudaFuncSetAttribute(final_kernel, cudaFuncAttributeMaxDynamicSharedMemorySize, DSM_FIN);

    topk_kernel  <<<dim3(5, BB), 1024>>>(obj);
    decode_kernel<<<(BB*KTOT + 255)/256, 256>>>(obj, deltas, anchors);
    nms_kernel   <<<dim3(5, BB), 512, DSM_NMS>>>();
    final_kernel <<<BB, 1024, DSM_FIN>>>(out);
}

// round 6
// speedup vs baseline: 2.0715x; 2.0715x over previous
#include <cuda_runtime.h>

#define BB   8
#define ATOT 196416
#define KTOT 4576
#define BXC  4.135166556742356f   /* log(1000/16) */
#define ROWW 16
#define CANDCAP 2048

__constant__ int c_ln[5]    = {147456,36864,9216,2304,576};
__constant__ int c_loff[5]  = {0,147456,184320,193536,195840};
__constant__ int c_lk[5]    = {1000,1000,1000,1000,576};
__constant__ int c_lkoff[5] = {0,1000,2000,3000,4000};

__device__ int    g_selidx[BB*KTOT];
__device__ float4 g_boxes [BB*KTOT];
__device__ float  g_scores[BB*KTOT];
__device__ int    g_valid [BB*KTOT];
__device__ int    g_keep  [BB*KTOT];
__device__ int    g_maxb  [BB];

__device__ __forceinline__ unsigned fkey(float f){
    unsigned u = __float_as_uint(f);
    return (u & 0x80000000u) ? ~u : (u | 0x80000000u);
}
__device__ __forceinline__ unsigned long long pack_ki(unsigned u, unsigned i){
    return ((unsigned long long)u << 32) | (unsigned long long)(0xFFFFFFFFu - i);
}

__device__ void bitonic_desc_u64(unsigned long long* a, int n){
    for (int k = 2; k <= n; k <<= 1)
        for (int j = k >> 1; j > 0; j >>= 1){
            for (int idx = threadIdx.x; idx < n; idx += blockDim.x){
                int ixj = idx ^ j;
                if (ixj > idx){
                    unsigned long long x = a[idx], y = a[ixj];
                    bool sw = ((idx & k) == 0) ? (x < y) : (x > y);
                    if (sw){ a[idx] = y; a[ixj] = x; }
                }
            }
            __syncthreads();
        }
}
__device__ void bitonic_asc_u32(unsigned* a, int n){
    for (int k = 2; k <= n; k <<= 1)
        for (int j = k >> 1; j > 0; j >>= 1){
            for (int idx = threadIdx.x; idx < n; idx += blockDim.x){
                int ixj = idx ^ j;
                if (ixj > idx){
                    unsigned x = a[idx], y = a[ixj];
                    bool sw = ((idx & k) == 0) ? (x > y) : (x < y);
                    if (sw){ a[idx] = y; a[ixj] = x; }
                }
            }
            __syncthreads();
        }
}

/* parallel threshold find: largest t with suffix-count(hist, t) >= k.
   Destroys hist; uses tmp as scan double-buffer. Caller syncs before entry. */
__device__ void find_thresh(unsigned* hist, unsigned* tmp, int NB, int k,
                            int* o_t, int* o_rem){
    unsigned* src = hist; unsigned* dst = tmp;
    for (int st = 1; st < NB; st <<= 1){
        for (int x = threadIdx.x; x < NB; x += blockDim.x){
            unsigned v = src[x];
            if (x + st < NB) v += src[x + st];
            dst[x] = v;
        }
        __syncthreads();
        unsigned* sw = src; src = dst; dst = sw;
    }
    for (int x = threadIdx.x; x < NB; x += blockDim.x){
        unsigned St = src[x];
        unsigned Sn = (x + 1 < NB) ? src[x + 1] : 0u;
        if (St >= (unsigned)k && Sn < (unsigned)k){ *o_t = x; *o_rem = k - (int)Sn; }
    }
    __syncthreads();
}

/* ---------------- K1: exact per-(batch,level) top-k (radix select, 2 data scans) ----------- */
__global__ __launch_bounds__(1024) void topk_kernel(const float* __restrict__ obj){
    __shared__ unsigned hist[2048];
    __shared__ unsigned tmp[2048];
    __shared__ unsigned long long sel[1024];
    __shared__ unsigned ties[1024];
    __shared__ unsigned long long cand[CANDCAP];
    __shared__ int s_t, s_rem, s_ngt, s_nc, s_neq;

    int lev = blockIdx.x, b = blockIdx.y, tid = threadIdx.x;
    if (lev == 0 && b == 0 && tid < BB) g_maxb[tid] = 0;
    int n = c_ln[lev], k = c_lk[lev];
    const float* p = obj + (size_t)b*ATOT + c_loff[lev];
    int lane = tid & 31;

    for (int i = tid; i < 2048; i += 1024) hist[i] = 0;
    if (tid == 0){ s_ngt = 0; s_nc = 0; s_neq = 0; }
    __syncthreads();

    /* pass 1: bins = key >> 21 */
    for (int base = 0; base < n; base += 1024){
        int i = base + tid;
        unsigned bin = 0xFFFFFFFFu;
        if (i < n) bin = fkey(p[i]) >> 21;
        unsigned mm = __match_any_sync(0xFFFFFFFFu, bin);
        if (bin != 0xFFFFFFFFu && lane == (__ffs(mm)-1)) atomicAdd(&hist[bin], __popc(mm));
    }
    __syncthreads();
    find_thresh(hist, tmp, 2048, k, &s_t, &s_rem);
    unsigned t1 = (unsigned)s_t; int k1 = s_rem;

    /* pass 2: histogram mid bits of bin==t1; compact candidates; collect strictly-above */
    for (int i = tid; i < 2048; i += 1024) hist[i] = 0;
    __syncthreads();
    for (int base = 0; base < n; base += 1024){
        int i = base + tid;
        unsigned bin = 0xFFFFFFFFu;
        if (i < n){
            unsigned u = fkey(p[i]);
            unsigned b31 = u >> 21;
            if (b31 > t1){
                int q = atomicAdd(&s_ngt, 1);
                sel[q] = pack_ki(u, (unsigned)i);
            } else if (b31 == t1){
                int q = atomicAdd(&s_nc, 1);
                if (q < CANDCAP) cand[q] = pack_ki(u, (unsigned)i);
                bin = (u >> 10) & 0x7FFu;
            }
        }
        unsigned mm = __match_any_sync(0xFFFFFFFFu, bin);
        if (bin != 0xFFFFFFFFu && lane == (__ffs(mm)-1)) atomicAdd(&hist[bin], __popc(mm));
    }
    __syncthreads();
    int nc = s_nc;
    bool fb = (nc > CANDCAP);          /* fallback: rescan global data */
    find_thresh(hist, tmp, 2048, k1, &s_t, &s_rem);
    unsigned t2 = (unsigned)s_t; int k2 = s_rem;
    unsigned pre22 = (t1 << 11) | t2;

    /* pass 3: low 10 bits among 22-bit prefix match */
    hist[tid & 1023] = 0;   /* blockDim==1024 covers all */
    __syncthreads();
    if (!fb){
        for (int base = 0; base < nc; base += 1024){
            int i = base + tid;
            unsigned bin = 0xFFFFFFFFu;
            if (i < nc){
                unsigned u = (unsigned)(cand[i] >> 32);
                if (((u >> 10) & 0x7FFu) == t2) bin = u & 0x3FFu;
            }
            unsigned mm = __match_any_sync(0xFFFFFFFFu, bin);
            if (bin != 0xFFFFFFFFu && lane == (__ffs(mm)-1)) atomicAdd(&hist[bin], __popc(mm));
        }
    } else {
        for (int base = 0; base < n; base += 1024){
            int i = base + tid;
            unsigned bin = 0xFFFFFFFFu;
            if (i < n){
                unsigned u = fkey(p[i]);
                if ((u >> 10) == pre22) bin = u & 0x3FFu;
            }
            unsigned mm = __match_any_sync(0xFFFFFFFFu, bin);
            if (bin != 0xFFFFFFFFu && lane == (__ffs(mm)-1)) atomicAdd(&hist[bin], __popc(mm));
        }
    }
    __syncthreads();
    find_thresh(hist, tmp, 1024, k2, &s_t, &s_rem);
    unsigned T = (pre22 << 10) | (unsigned)s_t;
    int rem = s_rem;

    /* collect remaining strictly-above + ties at T */
    if (!fb){
        for (int i = tid; i < nc; i += 1024){
            unsigned long long cv = cand[i];
            unsigned u = (unsigned)(cv >> 32);
            if (u > T){
                int q = atomicAdd(&s_ngt, 1); sel[q] = cv;
            } else if (u == T){
                int q = atomicAdd(&s_neq, 1);
                if (q < 1024) ties[q] = 0xFFFFFFFFu - (unsigned)(cv & 0xFFFFFFFFull);
            }
        }
    } else {
        for (int i = tid; i < n; i += 1024){
            unsigned u = fkey(p[i]);
            if ((u >> 21) == t1){
                if (u > T){
                    int q = atomicAdd(&s_ngt, 1); sel[q] = pack_ki(u, (unsigned)i);
                } else if (u == T){
                    int q = atomicAdd(&s_neq, 1);
                    if (q < 1024) ties[q] = (unsigned)i;
                }
            }
        }
    }
    __syncthreads();
    int ngt = s_ngt, neq = min(s_neq, 1024);
    for (int i = neq + tid; i < 1024; i += 1024) ties[i] = 0xFFFFFFFFu;
    __syncthreads();
    bitonic_asc_u32(ties, 1024);            /* smallest indices first among ties */
    for (int r = tid; r < rem; r += 1024)
        sel[ngt + r] = ((unsigned long long)T << 32) | (unsigned long long)(0xFFFFFFFFu - ties[r]);
    for (int r = k + tid; r < 1024; r += 1024) sel[r] = 0ull;
    __syncthreads();
    bitonic_desc_u64(sel, 1024);            /* (value desc, idx asc) = lax.top_k order */
    int koff = c_lkoff[lev], off = c_loff[lev];
    for (int r = tid; r < k; r += 1024){
        unsigned li = 0xFFFFFFFFu - (unsigned)(sel[r] & 0xFFFFFFFFull);
        g_selidx[b*KTOT + koff + r] = off + (int)li;
    }
}

/* ---------------- K2: decode + clip + score + validity + per-image coord max ---------------- */
__global__ void decode_kernel(const float* __restrict__ obj,
                              const float* __restrict__ deltas,
                              const float* __restrict__ anchors){
    int e = blockIdx.x*blockDim.x + threadIdx.x;
    if (e >= BB*KTOT) return;
    int b = e / KTOT;
    int a = g_selidx[e];
    const float* an = anchors + 4*(size_t)a;
    float ax1 = an[0], ay1 = an[1], ax2 = an[2], ay2 = an[3];
    float wa = ax2 - ax1, ha = ay2 - ay1;
    float cxa = ax1 + 0.5f*wa, cya = ay1 + 0.5f*ha;
    const float* d = deltas + ((size_t)b*ATOT + a)*4;
    float dx = d[0], dy = d[1];
    float dw = fminf(d[2], BXC), dh = fminf(d[3], BXC);
    float pcx = dx*wa + cxa, pcy = dy*ha + cya;
    float pw = expf(dw)*wa, ph = expf(dh)*ha;
    float x1 = pcx - 0.5f*pw, y1 = pcy - 0.5f*ph;
    float x2 = pcx + 0.5f*pw, y2 = pcy + 0.5f*ph;
    x1 = fminf(fmaxf(x1, 0.f), 1024.f);
    y1 = fminf(fmaxf(y1, 0.f), 768.f);
    x2 = fminf(fmaxf(x2, 0.f), 1024.f);
    y2 = fminf(fmaxf(y2, 0.f), 768.f);
    float xo = obj[(size_t)b*ATOT + a];
    float s = 1.f/(1.f + expf(-xo));
    int v = ((x2 - x1) >= 1.0f) && ((y2 - y1) >= 1.0f) && (s >= 0.f);
    g_boxes[e]  = make_float4(x1, y1, x2, y2);
    g_scores[e] = s;
    g_valid[e]  = v;
    float mx = fmaxf(fmaxf(x1, y1), fmaxf(x2, y2));
    atomicMax(&g_maxb[b], __float_as_int(mx));
}

/* ---------------- K3: per-(batch,level) greedy NMS (division-free, broadcast LDS) ----------- */
__global__ __launch_bounds__(512) void nms_kernel(){
    extern __shared__ unsigned char dsm_nms[];
    float* sx1 = (float*)dsm_nms;
    float* sy1 = sx1 + 1024;
    float* sx2 = sy1 + 1024;
    float* sy2 = sx2 + 1024;
    float* sar = sy2 + 1024;
    unsigned long long* mat = (unsigned long long*)(sar + 1024);  /* 1024 rows x 16 words */
    __shared__ unsigned long long keepw[ROWW];
    __shared__ unsigned slist[1024];
    __shared__ unsigned char vsm[1024];
    __shared__ int s_ns;

    int lev = blockIdx.x, b = blockIdx.y, tid = threadIdx.x;
    int m = c_lk[lev];
    int base = b*KTOT + c_lkoff[lev];
    float c = (float)lev * (__int_as_float(g_maxb[b]) + 1.0f);
    if (tid == 0) s_ns = 0;
    for (int i = tid; i < m; i += blockDim.x){
        float4 bx = g_boxes[base + i];
        float nx1 = bx.x + c, ny1 = bx.y + c, nx2 = bx.z + c, ny2 = bx.w + c;
        sx1[i] = nx1; sy1[i] = ny1; sx2[i] = nx2; sy2[i] = ny2;
        sar[i] = (nx2 - nx1)*(ny2 - ny1);
        vsm[i] = (unsigned char)g_valid[base + i];
    }
    __syncthreads();
    if (tid < ROWW){
        unsigned long long kw = 0ull;
        int j0 = tid << 6;
        for (int t = 0; t < 64; ++t){
            int i = j0 + t;
            if (i < m && vsm[i]) kw |= (1ull << t);
        }
        keepw[tid] = kw;
    }
    /* phase A: suppression bit-matrix. i-major so a warp's 32 lanes share j -> LDS broadcast */
    for (int i = tid; i < m; i += blockDim.x){
        float ax1 = sx1[i], ay1 = sy1[i], ax2 = sx2[i], ay2 = sy2[i], aa = sar[i];
        int wbase = i & ~31;   /* uniform per warp */
        #pragma unroll
        for (int w = 0; w < ROWW; ++w){
            int j0 = w << 6;
            if (j0 >= m || (j0 + 64 <= wbase + 1)){ mat[i*ROWW + w] = 0ull; continue; }
            unsigned long long bits = 0ull;
            int jend = min(j0 + 64, m);
            for (int j = j0; j < jend; ++j){
                float iw = fmaxf(fminf(ax2, sx2[j]) - fmaxf(ax1, sx1[j]), 0.f);
                float ih = fmaxf(fminf(ay2, sy2[j]) - fmaxf(ay1, sy1[j]), 0.f);
                float inter = iw*ih;
                /* iou > 0.7  <=>  inter > 0.7*union (union >= inter >= 0) */
                bool sup = (j > i) && (inter > 0.7f*(aa + sar[j] - inter));
                if (sup) bits |= (1ull << (j - j0));
            }
            mat[i*ROWW + w] = bits;
        }
    }
    __syncthreads();
    /* only rows that can suppress something need the serial pass */
    for (int i = tid; i < m; i += blockDim.x){
        unsigned long long any = 0ull;
        #pragma unroll
        for (int w = 0; w < ROWW; ++w) any |= mat[i*ROWW + w];
        if (any){ int p = atomicAdd(&s_ns, 1); slist[p] = (unsigned)i; }
    }
    __syncthreads();
    int ns = s_ns;
    for (int i = ns + tid; i < 1024; i += blockDim.x) slist[i] = 0xFFFFFFFFu;
    __syncthreads();
    bitonic_asc_u32(slist, 1024);
    /* phase B: serial greedy over suppressor rows only (warp 0) */
    if (tid < 32){
        for (int s = 0; s < ns; ++s){
            int i = (int)slist[s];
            unsigned long long kw = keepw[i >> 6];
            if ((kw >> (i & 63)) & 1ull){
                if (tid < ROWW) keepw[tid] &= ~mat[i*ROWW + tid];
            }
            __syncwarp();
        }
    }
    __syncthreads();
    for (int i = tid; i < m; i += blockDim.x)
        g_keep[base + i] = (int)((keepw[i >> 6] >> (i & 63)) & 1ull);
}

/* ---------------- K4: per-image post-NMS top-1000 via radix select + 1024 sort -------------- */
__global__ __launch_bounds__(1024) void final_kernel(float* __restrict__ out){
    __shared__ unsigned skey[KTOT];
    __shared__ unsigned hist[2048];
    __shared__ unsigned tmp[2048];
    __shared__ unsigned long long sel[1024];
    __shared__ unsigned ties[1024];
    __shared__ int s_t, s_rem, s_ngt, s_neq;

    int b = blockIdx.x, tid = threadIdx.x, lane = tid & 31;
    const int K2 = 1000;

    for (int i = tid; i < KTOT; i += 1024){
        unsigned kk = 0u;
        if (g_keep[b*KTOT + i]) kk = __float_as_uint(g_scores[b*KTOT + i]) | 0x80000000u;
        skey[i] = kk;
    }
    for (int i = tid; i < 2048; i += 1024) hist[i] = 0;
    if (tid == 0){ s_ngt = 0; s_neq = 0; }
    __syncthreads();
    /* pass 1 */
    for (int base = 0; base < KTOT; base += 1024){
        int i = base + tid;
        unsigned bin = 0xFFFFFFFFu;
        if (i < KTOT) bin = skey[i] >> 21;
        unsigned mm = __match_any_sync(0xFFFFFFFFu, bin);
        if (bin != 0xFFFFFFFFu && lane == (__ffs(mm)-1)) atomicAdd(&hist[bin], __popc(mm));
    }
    __syncthreads();
    find_thresh(hist, tmp, 2048, K2, &s_t, &s_rem);
    unsigned t1 = (unsigned)s_t; int k1 = s_rem;
    /* pass 2 + collect strictly above bin */
    for (int i = tid; i < 2048; i += 1024) hist[i] = 0;
    __syncthreads();
    for (int base = 0; base < KTOT; base += 1024){
        int i = base + tid;
        unsigned bin = 0xFFFFFFFFu;
        if (i < KTOT){
            unsigned u = skey[i];
            unsigned b31 = u >> 21;
            if (b31 > t1){ int q = atomicAdd(&s_ngt, 1); sel[q] = pack_ki(u, (unsigned)i); }
            else if (b31 == t1) bin = (u >> 10) & 0x7FFu;
        }
        unsigned mm = __match_any_sync(0xFFFFFFFFu, bin);
        if (bin != 0xFFFFFFFFu && lane == (__ffs(mm)-1)) atomicAdd(&hist[bin], __popc(mm));
    }
    __syncthreads();
    find_thresh(hist, tmp, 2048, k1, &s_t, &s_rem);
    unsigned t2 = (unsigned)s_t; int k2 = s_rem;
    unsigned pre22 = (t1 << 11) | t2;
    hist[tid & 1023] = 0;
    __syncthreads();
    /* pass 3 */
    for (int base = 0; base < KTOT; base += 1024){
        int i = base + tid;
        unsigned bin = 0xFFFFFFFFu;
        if (i < KTOT){
            unsigned u = skey[i];
            if ((u >> 10) == pre22) bin = u & 0x3FFu;
        }
        unsigned mm = __match_any_sync(0xFFFFFFFFu, bin);
        if (bin != 0xFFFFFFFFu && lane == (__ffs(mm)-1)) atomicAdd(&hist[bin], __popc(mm));
    }
    __syncthreads();
    find_thresh(hist, tmp, 1024, k2, &s_t, &s_rem);
    unsigned T = (pre22 << 10) | (unsigned)s_t;
    int rem = s_rem;
    /* collect */
    for (int i = tid; i < KTOT; i += 1024){
        unsigned u = skey[i];
        if ((u >> 21) == t1){
            if (u > T){ int q = atomicAdd(&s_ngt, 1); sel[q] = pack_ki(u, (unsigned)i); }
            else if (u == T){
                int q = atomicAdd(&s_neq, 1);
                if (q < 1024) ties[q] = (unsigned)i;
            }
        }
    }
    __syncthreads();
    int ngt = s_ngt, neq = min(s_neq, 1024);
    for (int i = neq + tid; i < 1024; i += 1024) ties[i] = 0xFFFFFFFFu;
    __syncthreads();
    bitonic_asc_u32(ties, 1024);
    for (int r = tid; r < rem; r += 1024)
        sel[ngt + r] = ((unsigned long long)T << 32) | (unsigned long long)(0xFFFFFFFFu - ties[r]);
    for (int r = K2 + tid; r < 1024; r += 1024) sel[r] = 0ull;
    __syncthreads();
    bitonic_desc_u64(sel, 1024);
    for (int r = tid; r < K2; r += 1024){
        unsigned long long cc = sel[r];
        float* o = out + ((size_t)b*1000 + r)*5;
        if ((unsigned)(cc >> 32) & 0x80000000u){   /* kept keys always have bit31 set */
            int pos = (int)(0xFFFFFFFFu - (unsigned)(cc & 0xFFFFFFFFull));
            float4 bx = g_boxes[b*KTOT + pos];
            o[0] = bx.x; o[1] = bx.y; o[2] = bx.z; o[3] = bx.w;
            o[4] = g_scores[b*KTOT + pos];
        } else {
            o[0] = 0.f; o[1] = 0.f; o[2] = 0.f; o[3] = 0.f; o[4] = 0.f;
        }
    }
}

extern "C" void kernel_launch(void* const* d_in, const int* in_sizes, int n_in,
                              void* d_out, int out_size){
    const float* obj     = (const float*)d_in[0];
    const float* deltas  = (const float*)d_in[1];
    const float* anchors = (const float*)d_in[2];
    float* out = (float*)d_out;

    const int DSM_NMS = 5*1024*4 + 1024*ROWW*8;   /* 151552 */
    cudaFuncSetAttribute(nms_kernel, cudaFuncAttributeMaxDynamicSharedMemorySize, DSM_NMS);

    topk_kernel  <<<dim3(5, BB), 1024>>>(obj);
    decode_kernel<<<(BB*KTOT + 255)/256, 256>>>(obj, deltas, anchors);
    nms_kernel   <<<dim3(5, BB), 512, DSM_NMS>>>();
    final_kernel <<<BB, 1024>>>(out);
}

// round 9
// speedup vs baseline: 4.2286x; 2.0414x over previous
#include <cuda_runtime.h>

#define BB   8
#define ATOT 196416
#define KTOT 4576
#define BXC  4.135166556742356f   /* log(1000/16) */
#define ROWW 16
#define CH1  16
#define CAP  8192
#define NCELL 40

__constant__ int c_ln[5]    = {147456,36864,9216,2304,576};
__constant__ int c_loff[5]  = {0,147456,184320,193536,195840};
__constant__ int c_lk[5]    = {1000,1000,1000,1000,576};
__constant__ int c_lkoff[5] = {0,1000,2000,3000,4000};

__device__ unsigned            g_hist2[NCELL][2048];
__device__ int                 g_t1a[NCELL];
__device__ int                 g_cnt[NCELL];
__device__ unsigned long long  g_cand[NCELL][CAP];
__device__ unsigned long long  g_mat2[NCELL][1024][ROWW];
__device__ unsigned long long  g_supmask[NCELL][16];
__device__ int    g_selidx[BB*KTOT];
__device__ float4 g_boxes [BB*KTOT];
__device__ float  g_scores[BB*KTOT];
__device__ int    g_valid [BB*KTOT];
__device__ int    g_keep  [BB*KTOT];
__device__ int    g_maxb  [BB];

__device__ __forceinline__ unsigned fkey(float f){
    unsigned u = __float_as_uint(f);
    return (u & 0x80000000u) ? ~u : (u | 0x80000000u);
}
__device__ __forceinline__ unsigned long long pack_ki(unsigned u, unsigned i){
    return ((unsigned long long)u << 32) | (unsigned long long)(0xFFFFFFFFu - i);
}

__device__ void bitonic_desc_u64(unsigned long long* a, int n){
    for (int k = 2; k <= n; k <<= 1)
        for (int j = k >> 1; j > 0; j >>= 1){
            for (int idx = threadIdx.x; idx < n; idx += blockDim.x){
                int ixj = idx ^ j;
                if (ixj > idx){
                    unsigned long long x = a[idx], y = a[ixj];
                    bool sw = ((idx & k) == 0) ? (x < y) : (x > y);
                    if (sw){ a[idx] = y; a[ixj] = x; }
                }
            }
            __syncthreads();
        }
}
__device__ void bitonic_asc_u32(unsigned* a, int n){
    for (int k = 2; k <= n; k <<= 1)
        for (int j = k >> 1; j > 0; j >>= 1){
            for (int idx = threadIdx.x; idx < n; idx += blockDim.x){
                int ixj = idx ^ j;
                if (ixj > idx){
                    unsigned x = a[idx], y = a[ixj];
                    bool sw = ((idx & k) == 0) ? (x > y) : (x < y);
                    if (sw){ a[idx] = y; a[ixj] = x; }
                }
            }
            __syncthreads();
        }
}

/* largest t with suffix-count(hist,t) >= k; destroys hist, uses tmp. */
__device__ void find_thresh(unsigned* hist, unsigned* tmp, int NB, int k,
                            int* o_t, int* o_rem){
    unsigned* src = hist; unsigned* dst = tmp;
    for (int st = 1; st < NB; st <<= 1){
        for (int x = threadIdx.x; x < NB; x += blockDim.x){
            unsigned v = src[x];
            if (x + st < NB) v += src[x + st];
            dst[x] = v;
        }
        __syncthreads();
        unsigned* sw = src; src = dst; dst = sw;
    }
    for (int x = threadIdx.x; x < NB; x += blockDim.x){
        unsigned St = src[x];
        unsigned Sn = (x + 1 < NB) ? src[x + 1] : 0u;
        if (St >= (unsigned)k && Sn < (unsigned)k){ *o_t = x; *o_rem = k - (int)Sn; }
    }
    __syncthreads();
}

/* ---------------- K0: zero per-launch scratch ---------------- */
__global__ void init_kernel(){
    int cell = blockIdx.x, tid = threadIdx.x;
    for (int i = tid; i < 2048; i += 256) g_hist2[cell][i] = 0;
    if (tid == 0) g_cnt[cell] = 0;
    if (tid < 16) g_supmask[cell][tid] = 0ull;
    if (cell == 0 && tid < BB) g_maxb[tid] = 0;
}

/* ---------------- K1a: chunked histogram of top-11 key bits ---------------- */
__global__ __launch_bounds__(256) void hist_kernel(const float* __restrict__ obj){
    __shared__ unsigned h[2048];
    int lev = blockIdx.x, b = blockIdx.y, ch = blockIdx.z, tid = threadIdx.x;
    int cell = b*5 + lev;
    int n = c_ln[lev];
    int chunk = (n + CH1 - 1)/CH1;
    int s = ch*chunk, e = min(s + chunk, n);
    const float* p = obj + (size_t)b*ATOT + c_loff[lev];
    int lane = tid & 31;
    for (int i = tid; i < 2048; i += 256) h[i] = 0;
    __syncthreads();
    for (int base = s; base < e; base += 256){
        int i = base + tid;
        unsigned bin = 0xFFFFFFFFu;
        if (i < e) bin = fkey(p[i]) >> 21;
        unsigned mm = __match_any_sync(0xFFFFFFFFu, bin);
        if (bin != 0xFFFFFFFFu && lane == (__ffs(mm)-1)) atomicAdd(&h[bin], __popc(mm));
    }
    __syncthreads();
    for (int x = tid; x < 2048; x += 256)
        if (h[x]) atomicAdd(&g_hist2[cell][x], h[x]);
}

/* ---------------- K1b: per-(b,lev) pass-1 threshold ---------------- */
__global__ __launch_bounds__(512) void thr1_kernel(){
    __shared__ unsigned hist[2048], tmp[2048];
    __shared__ int s_t, s_rem;
    int lev = blockIdx.x, b = blockIdx.y, tid = threadIdx.x;
    int cell = b*5 + lev, k = c_lk[lev];
    for (int i = tid; i < 2048; i += 512) hist[i] = g_hist2[cell][i];
    __syncthreads();
    find_thresh(hist, tmp, 2048, k, &s_t, &s_rem);
    if (tid == 0) g_t1a[cell] = s_t;
}

/* ---------------- K1c: chunked candidate compaction (bin >= t1) ---------------- */
__global__ __launch_bounds__(256) void cand_kernel(const float* __restrict__ obj){
    int lev = blockIdx.x, b = blockIdx.y, ch = blockIdx.z, tid = threadIdx.x;
    int cell = b*5 + lev;
    int n = c_ln[lev];
    int chunk = (n + CH1 - 1)/CH1;
    int s = ch*chunk, e = min(s + chunk, n);
    const float* p = obj + (size_t)b*ATOT + c_loff[lev];
    unsigned t1 = (unsigned)g_t1a[cell];
    int lane = tid & 31;
    for (int base = s; base < e; base += 256){
        int i = base + tid;
        unsigned u = 0;
        bool pred = false;
        if (i < e){ u = fkey(p[i]); pred = (u >> 21) >= t1; }
        unsigned mask = __ballot_sync(0xFFFFFFFFu, pred);
        int cnt = __popc(mask);
        int pos = 0;
        if (lane == 0 && cnt) pos = atomicAdd(&g_cnt[cell], cnt);
        pos = __shfl_sync(0xFFFFFFFFu, pos, 0);
        int my = pos + __popc(mask & ((1u << lane) - 1));
        if (pred && my < CAP) g_cand[cell][my] = pack_ki(u, (unsigned)i);
    }
}

/* ---------------- K1d: exact per-(b,lev) top-k over compact candidates ---------------- */
__global__ __launch_bounds__(512) void select_kernel(const float* __restrict__ obj){
    extern __shared__ unsigned char dsm_sel[];
    unsigned long long* scand = (unsigned long long*)dsm_sel;       /* CAP  */
    unsigned long long* sel   = scand + CAP;                        /* 1024 */
    unsigned* hist = (unsigned*)(sel + 1024);                       /* 2048 */
    unsigned* tmp  = hist + 2048;                                   /* 2048 */
    unsigned* ties = tmp + 2048;                                    /* 1024 */
    __shared__ int s_t, s_rem, s_ngt, s_neq;

    int lev = blockIdx.x, b = blockIdx.y, tid = threadIdx.x;
    int cell = b*5 + lev;
    int n = c_ln[lev], k = c_lk[lev];
    const float* p = obj + (size_t)b*ATOT + c_loff[lev];
    int lane = tid & 31;
    unsigned t1 = (unsigned)g_t1a[cell];
    int nc = g_cnt[cell];
    bool fb = (nc > CAP);

    if (tid == 0){ s_ngt = 0; s_neq = 0; }
    if (!fb) for (int i = tid; i < nc; i += 512) scand[i] = g_cand[cell][i];
    for (int i = tid; i < 2048; i += 512) hist[i] = 0;
    __syncthreads();

    /* mid-bits histogram of bin==t1; collect strictly-above bins */
    if (!fb){
        for (int base = 0; base < nc; base += 512){
            int i = base + tid;
            unsigned bin = 0xFFFFFFFFu;
            if (i < nc){
                unsigned long long cv = scand[i];
                unsigned u = (unsigned)(cv >> 32);
                if ((u >> 21) > t1){ int q = atomicAdd(&s_ngt, 1); sel[q] = cv; }
                else bin = (u >> 10) & 0x7FFu;          /* bin == t1 guaranteed */
            }
            unsigned mm = __match_any_sync(0xFFFFFFFFu, bin);
            if (bin != 0xFFFFFFFFu && lane == (__ffs(mm)-1)) atomicAdd(&hist[bin], __popc(mm));
        }
    } else {
        for (int base = 0; base < n; base += 512){
            int i = base + tid;
            unsigned bin = 0xFFFFFFFFu;
            if (i < n){
                unsigned u = fkey(p[i]);
                unsigned b31 = u >> 21;
                if (b31 > t1){ int q = atomicAdd(&s_ngt, 1); sel[q] = pack_ki(u, (unsigned)i); }
                else if (b31 == t1) bin = (u >> 10) & 0x7FFu;
            }
            unsigned mm = __match_any_sync(0xFFFFFFFFu, bin);
            if (bin != 0xFFFFFFFFu && lane == (__ffs(mm)-1)) atomicAdd(&hist[bin], __popc(mm));
        }
    }
    __syncthreads();
    int k1 = k - s_ngt;
    find_thresh(hist, tmp, 2048, k1, &s_t, &s_rem);
    unsigned t2 = (unsigned)s_t; int k2 = s_rem;
    unsigned pre22 = (t1 << 11) | t2;

    for (int i = tid; i < 1024; i += 512) hist[i] = 0;
    __syncthreads();
    if (!fb){
        for (int base = 0; base < nc; base += 512){
            int i = base + tid;
            unsigned bin = 0xFFFFFFFFu;
            if (i < nc){
                unsigned u = (unsigned)(scand[i] >> 32);
                if ((u >> 10) == pre22) bin = u & 0x3FFu;
            }
            unsigned mm = __match_any_sync(0xFFFFFFFFu, bin);
            if (bin != 0xFFFFFFFFu && lane == (__ffs(mm)-1)) atomicAdd(&hist[bin], __popc(mm));
        }
    } else {
        for (int base = 0; base < n; base += 512){
            int i = base + tid;
            unsigned bin = 0xFFFFFFFFu;
            if (i < n){
                unsigned u = fkey(p[i]);
                if ((u >> 10) == pre22) bin = u & 0x3FFu;
            }
            unsigned mm = __match_any_sync(0xFFFFFFFFu, bin);
            if (bin != 0xFFFFFFFFu && lane == (__ffs(mm)-1)) atomicAdd(&hist[bin], __popc(mm));
        }
    }
    __syncthreads();
    find_thresh(hist, tmp, 1024, k2, &s_t, &s_rem);
    unsigned T = (pre22 << 10) | (unsigned)s_t;
    int rem = s_rem;

    /* collect remaining strictly-above (prefix==t1) + ties at T */
    if (!fb){
        for (int i = tid; i < nc; i += 512){
            unsigned long long cv = scand[i];
            unsigned u = (unsigned)(cv >> 32);
            if ((u >> 21) == t1){
                if (u > T){ int q = atomicAdd(&s_ngt, 1); sel[q] = cv; }
                else if (u == T){
                    int q = atomicAdd(&s_neq, 1);
                    if (q < 1024) ties[q] = 0xFFFFFFFFu - (unsigned)(cv & 0xFFFFFFFFull);
                }
            }
        }
    } else {
        for (int i = tid; i < n; i += 512){
            unsigned u = fkey(p[i]);
            if ((u >> 21) == t1){
                if (u > T){ int q = atomicAdd(&s_ngt, 1); sel[q] = pack_ki(u, (unsigned)i); }
                else if (u == T){
                    int q = atomicAdd(&s_neq, 1);
                    if (q < 1024) ties[q] = (unsigned)i;
                }
            }
        }
    }
    __syncthreads();
    int ngt = s_ngt, neq = min(s_neq, 1024);
    if (neq > rem){   /* only then does tie ORDER matter for selection */
        for (int i = neq + tid; i < 1024; i += 512) ties[i] = 0xFFFFFFFFu;
        __syncthreads();
        bitonic_asc_u32(ties, 1024);
    }
    for (int r = tid; r < rem; r += 512)
        sel[ngt + r] = ((unsigned long long)T << 32) | (unsigned long long)(0xFFFFFFFFu - ties[r]);
    for (int r = k + tid; r < 1024; r += 512) sel[r] = 0ull;
    __syncthreads();
    bitonic_desc_u64(sel, 1024);          /* (value desc, idx asc) = lax.top_k order */
    int koff = c_lkoff[lev], off = c_loff[lev];
    for (int r = tid; r < k; r += 512){
        unsigned li = 0xFFFFFFFFu - (unsigned)(sel[r] & 0xFFFFFFFFull);
        g_selidx[b*KTOT + koff + r] = off + (int)li;
    }
}

/* ---------------- K2: decode + clip + score + validity + per-image coord max ---------------- */
__global__ void decode_kernel(const float* __restrict__ obj,
                              const float* __restrict__ deltas,
                              const float* __restrict__ anchors){
    int e = blockIdx.x*blockDim.x + threadIdx.x;
    if (e >= BB*KTOT) return;
    int b = e / KTOT;
    int a = g_selidx[e];
    const float* an = anchors + 4*(size_t)a;
    float ax1 = an[0], ay1 = an[1], ax2 = an[2], ay2 = an[3];
    float wa = ax2 - ax1, ha = ay2 - ay1;
    float cxa = ax1 + 0.5f*wa, cya = ay1 + 0.5f*ha;
    const float* d = deltas + ((size_t)b*ATOT + a)*4;
    float dx = d[0], dy = d[1];
    float dw = fminf(d[2], BXC), dh = fminf(d[3], BXC);
    float pcx = dx*wa + cxa, pcy = dy*ha + cya;
    float pw = expf(dw)*wa, ph = expf(dh)*ha;
    float x1 = pcx - 0.5f*pw, y1 = pcy - 0.5f*ph;
    float x2 = pcx + 0.5f*pw, y2 = pcy + 0.5f*ph;
    x1 = fminf(fmaxf(x1, 0.f), 1024.f);
    y1 = fminf(fmaxf(y1, 0.f), 768.f);
    x2 = fminf(fmaxf(x2, 0.f), 1024.f);
    y2 = fminf(fmaxf(y2, 0.f), 768.f);
    float xo = obj[(size_t)b*ATOT + a];
    float s = 1.f/(1.f + expf(-xo));
    int v = ((x2 - x1) >= 1.0f) && ((y2 - y1) >= 1.0f) && (s >= 0.f);
    g_boxes[e]  = make_float4(x1, y1, x2, y2);
    g_scores[e] = s;
    g_valid[e]  = v;
    float mx = fmaxf(fmaxf(x1, y1), fmaxf(x2, y2));
    atomicMax(&g_maxb[b], __float_as_int(mx));
}

/* ---------------- K3a: NMS suppression matrix, row-strided across 320 blocks --------------- */
__global__ __launch_bounds__(128) void nmsA_kernel(){
    __shared__ float sx1[1024], sy1[1024], sx2[1024], sy2[1024], sar[1024];
    int lev = blockIdx.x, b = blockIdx.y, z = blockIdx.z, tid = threadIdx.x;
    int cell = b*5 + lev;
    int m = c_lk[lev];
    int base = b*KTOT + c_lkoff[lev];
    float c = (float)lev * (__int_as_float(g_maxb[b]) + 1.0f);
    for (int i = tid; i < m; i += 128){
        float4 bx = g_boxes[base + i];
        float nx1 = bx.x + c, ny1 = bx.y + c, nx2 = bx.z + c, ny2 = bx.w + c;
        sx1[i] = nx1; sy1[i] = ny1; sx2[i] = nx2; sy2[i] = ny2;
        sar[i] = (nx2 - nx1)*(ny2 - ny1);
    }
    __syncthreads();
    for (int i = z + 8*tid; i < m; i += 8*128){
        float ax1 = sx1[i], ay1 = sy1[i], ax2 = sx2[i], ay2 = sy2[i], aa = sar[i];
        unsigned long long wr[ROWW];
        unsigned long long any = 0ull;
        #pragma unroll
        for (int w = 0; w < ROWW; ++w){
            int j0 = w << 6;
            unsigned long long bits = 0ull;
            if (j0 < m && (j0 + 64 > i + 1)){
                int jend = min(j0 + 64, m);
                for (int j = j0; j < jend; ++j){
                    float iw = fmaxf(fminf(ax2, sx2[j]) - fmaxf(ax1, sx1[j]), 0.f);
                    float ih = fmaxf(fminf(ay2, sy2[j]) - fmaxf(ay1, sy1[j]), 0.f);
                    float inter = iw*ih;
                    bool sup = (j > i) && (inter > 0.7f*(aa + sar[j] - inter));
                    if (sup) bits |= (1ull << (j - j0));
                }
            }
            wr[w] = bits; any |= bits;
        }
        if (any){
            atomicOr(&g_supmask[cell][i >> 6], 1ull << (i & 63));
            #pragma unroll
            for (int w = 0; w < ROWW; ++w) g_mat2[cell][i][w] = wr[w];
        }
    }
}

/* ---------------- K3b: serial greedy over suppressor rows only --------------------------- */
__global__ __launch_bounds__(512) void nmsB_kernel(){
    extern __shared__ unsigned long long mat[];   /* 1024 x ROWW */
    __shared__ unsigned long long keepw[ROWW];
    __shared__ unsigned long long smask[ROWW];
    __shared__ unsigned kb32[32];
    int lev = blockIdx.x, b = blockIdx.y, tid = threadIdx.x;
    int cell = b*5 + lev;
    int m = c_lk[lev];
    int base = b*KTOT + c_lkoff[lev];
    if (tid < ROWW) smask[tid] = g_supmask[cell][tid];
    for (int i = tid; i < 1024; i += 512){
        int pred = (i < m) && g_valid[base + i];
        unsigned bits = __ballot_sync(0xFFFFFFFFu, pred);
        if ((tid & 31) == 0) kb32[i >> 5] = bits;
    }
    __syncthreads();
    if (tid < ROWW)
        keepw[tid] = ((unsigned long long)kb32[2*tid + 1] << 32) | (unsigned long long)kb32[2*tid];
    /* load suppressor rows only */
    for (int t = tid; t < 1024*ROWW; t += 512){
        int i = t >> 4, w = t & (ROWW - 1);
        if (i < m && ((smask[i >> 6] >> (i & 63)) & 1ull))
            mat[t] = g_mat2[cell][i][w];
    }
    __syncthreads();
    if (tid < 32){
        for (int w16 = 0; w16 < ROWW; ++w16){
            unsigned long long mw = smask[w16];
            while (mw){
                int bpos = __ffsll((long long)mw) - 1;
                mw &= mw - 1ull;
                int i = (w16 << 6) + bpos;
                if ((keepw[i >> 6] >> (i & 63)) & 1ull){
                    if (tid < ROWW) keepw[tid] &= ~mat[i*ROWW + tid];
                }
                __syncwarp();
            }
        }
    }
    __syncthreads();
    for (int i = tid; i < m; i += 512)
        g_keep[base + i] = (int)((keepw[i >> 6] >> (i & 63)) & 1ull);
}

/* ---------------- K4: per-image post-NMS top-1000 via radix select + 1024 sort ------------- */
__global__ __launch_bounds__(512) void final_kernel(float* __restrict__ out){
    __shared__ unsigned skey[KTOT];
    __shared__ unsigned hist[2048];
    __shared__ unsigned tmp[2048];
    __shared__ unsigned long long sel[1024];
    __shared__ unsigned ties[1024];
    __shared__ int s_t, s_rem, s_ngt, s_neq;

    int b = blockIdx.x, tid = threadIdx.x, lane = tid & 31;
    const int K2 = 1000;

    for (int i = tid; i < KTOT; i += 512){
        unsigned kk = 0u;
        if (g_keep[b*KTOT + i]) kk = __float_as_uint(g_scores[b*KTOT + i]) | 0x80000000u;
        skey[i] = kk;
    }
    for (int i = tid; i < 2048; i += 512) hist[i] = 0;
    if (tid == 0){ s_ngt = 0; s_neq = 0; }
    __syncthreads();
    for (int base = 0; base < KTOT; base += 512){
        int i = base + tid;
        unsigned bin = 0xFFFFFFFFu;
        if (i < KTOT) bin = skey[i] >> 21;
        unsigned mm = __match_any_sync(0xFFFFFFFFu, bin);
        if (bin != 0xFFFFFFFFu && lane == (__ffs(mm)-1)) atomicAdd(&hist[bin], __popc(mm));
    }
    __syncthreads();
    find_thresh(hist, tmp, 2048, K2, &s_t, &s_rem);
    unsigned t1 = (unsigned)s_t; int k1 = s_rem;
    for (int i = tid; i < 2048; i += 512) hist[i] = 0;
    __syncthreads();
    for (int base = 0; base < KTOT; base += 512){
        int i = base + tid;
        unsigned bin = 0xFFFFFFFFu;
        if (i < KTOT){
            unsigned u = skey[i];
            unsigned b31 = u >> 21;
            if (b31 > t1){ int q = atomicAdd(&s_ngt, 1); sel[q] = pack_ki(u, (unsigned)i); }
            else if (b31 == t1) bin = (u >> 10) & 0x7FFu;
        }
        unsigned mm = __match_any_sync(0xFFFFFFFFu, bin);
        if (bin != 0xFFFFFFFFu && lane == (__ffs(mm)-1)) atomicAdd(&hist[bin], __popc(mm));
    }
    __syncthreads();
    find_thresh(hist, tmp, 2048, k1, &s_t, &s_rem);
    unsigned t2 = (unsigned)s_t; int k2 = s_rem;
    unsigned pre22 = (t1 << 11) | t2;
    for (int i = tid; i < 1024; i += 512) hist[i] = 0;
    __syncthreads();
    for (int base = 0; base < KTOT; base += 512){
        int i = base + tid;
        unsigned bin = 0xFFFFFFFFu;
        if (i < KTOT){
            unsigned u = skey[i];
            if ((u >> 10) == pre22) bin = u & 0x3FFu;
        }
        unsigned mm = __match_any_sync(0xFFFFFFFFu, bin);
        if (bin != 0xFFFFFFFFu && lane == (__ffs(mm)-1)) atomicAdd(&hist[bin], __popc(mm));
    }
    __syncthreads();
    find_thresh(hist, tmp, 1024, k2, &s_t, &s_rem);
    unsigned T = (pre22 << 10) | (unsigned)s_t;
    int rem = s_rem;
    for (int i = tid; i < KTOT; i += 512){
        unsigned u = skey[i];
        if ((u >> 21) == t1){
            if (u > T){ int q = atomicAdd(&s_ngt, 1); sel[q] = pack_ki(u, (unsigned)i); }
            else if (u == T){
                int q = atomicAdd(&s_neq, 1);
                if (q < 1024) ties[q] = (unsigned)i;
            }
        }
    }
    __syncthreads();
    int ngt = s_ngt, neq = min(s_neq, 1024);
    if (neq > rem){
        for (int i = neq + tid; i < 1024; i += 512) ties[i] = 0xFFFFFFFFu;
        __syncthreads();
        bitonic_asc_u32(ties, 1024);
    }
    for (int r = tid; r < rem; r += 512)
        sel[ngt + r] = ((unsigned long long)T << 32) | (unsigned long long)(0xFFFFFFFFu - ties[r]);
    for (int r = K2 + tid; r < 1024; r += 512) sel[r] = 0ull;
    __syncthreads();
    bitonic_desc_u64(sel, 1024);
    for (int r = tid; r < K2; r += 512){
        unsigned long long cc = sel[r];
        float* o = out + ((size_t)b*1000 + r)*5;
        if ((unsigned)(cc >> 32) & 0x80000000u){
            int pos = (int)(0xFFFFFFFFu - (unsigned)(cc & 0xFFFFFFFFull));
            float4 bx = g_boxes[b*KTOT + pos];
            o[0] = bx.x; o[1] = bx.y; o[2] = bx.z; o[3] = bx.w;
            o[4] = g_scores[b*KTOT + pos];
        } else {
            o[0] = 0.f; o[1] = 0.f; o[2] = 0.f; o[3] = 0.f; o[4] = 0.f;
        }
    }
}

extern "C" void kernel_launch(void* const* d_in, const int* in_sizes, int n_in,
                              void* d_out, int out_size){
    const float* obj     = (const float*)d_in[0];
    const float* deltas  = (const float*)d_in[1];
    const float* anchors = (const float*)d_in[2];
    float* out = (float*)d_out;

    const int DSM_SEL = CAP*8 + 1024*8 + 2048*4 + 2048*4 + 1024*4;  /* 94208  */
    const int DSM_B   = 1024*ROWW*8;                                 /* 131072 */
    cudaFuncSetAttribute(select_kernel, cudaFuncAttributeMaxDynamicSharedMemorySize, DSM_SEL);
    cudaFuncSetAttribute(nmsB_kernel,   cudaFuncAttributeMaxDynamicSharedMemorySize, DSM_B);

    init_kernel  <<<NCELL, 256>>>();
    hist_kernel  <<<dim3(5, BB, CH1), 256>>>(obj);
    thr1_kernel  <<<dim3(5, BB), 512>>>();
    cand_kernel  <<<dim3(5, BB, CH1), 256>>>(obj);
    select_kernel<<<dim3(5, BB), 512, DSM_SEL>>>(obj);
    decode_kernel<<<(BB*KTOT + 255)/256, 256>>>(obj, deltas, anchors);
    nmsA_kernel  <<<dim3(5, BB, 8), 128>>>();
    nmsB_kernel  <<<dim3(5, BB), 512, DSM_B>>>();
    final_kernel <<<BB, 512>>>(out);
}

// round 12
// speedup vs baseline: 8.9685x; 2.1209x over previous
#include <cuda_runtime.h>

#define BB    8
#define ATOT  196416
#define KTOT  4576
#define BXC   4.135166556742356f   /* log(1000/16) */
#define ROWW  16
#define CH1   16
#define CHCAP 512
#define SCAP  (CH1*CHCAP)          /* 8192 */
#define NCELL 40

__constant__ int c_ln[5]    = {147456,36864,9216,2304,576};
__constant__ int c_loff[5]  = {0,147456,184320,193536,195840};
__constant__ int c_lk[5]    = {1000,1000,1000,1000,576};
__constant__ int c_lkoff[5] = {0,1000,2000,3000,4000};
/* static candidate guesses: fkey(2.0), fkey(1.5), fkey(0.5), take-all, take-all */
__constant__ unsigned c_guess[5] = {0xC0000000u, 0xBFC00000u, 0xBF000000u, 0u, 0u};

__device__ unsigned long long g_cand[NCELL][SCAP];
__device__ int                g_ccnt[NCELL][CH1];
__device__ unsigned long long g_mat2[NCELL][1024][ROWW];
__device__ int                g_suprow[NCELL][1024];
__device__ float4 g_boxes [BB*KTOT];
__device__ float  g_scores[BB*KTOT];
__device__ int    g_valid [BB*KTOT];
__device__ int    g_keep  [BB*KTOT];
__device__ int    g_maxb  [BB];

__device__ __forceinline__ unsigned fkey(float f){
    unsigned u = __float_as_uint(f);
    return (u & 0x80000000u) ? ~u : (u | 0x80000000u);
}
__device__ __forceinline__ unsigned long long pack_ki(unsigned u, unsigned i){
    return ((unsigned long long)u << 32) | (unsigned long long)(0xFFFFFFFFu - i);
}

__device__ void bitonic_desc_u64(unsigned long long* a, int n){
    for (int k = 2; k <= n; k <<= 1)
        for (int j = k >> 1; j > 0; j >>= 1){
            for (int idx = threadIdx.x; idx < n; idx += blockDim.x){
                int ixj = idx ^ j;
                if (ixj > idx){
                    unsigned long long x = a[idx], y = a[ixj];
                    bool sw = ((idx & k) == 0) ? (x < y) : (x > y);
                    if (sw){ a[idx] = y; a[ixj] = x; }
                }
            }
            __syncthreads();
        }
}
__device__ void bitonic_asc_u32(unsigned* a, int n){
    for (int k = 2; k <= n; k <<= 1)
        for (int j = k >> 1; j > 0; j >>= 1){
            for (int idx = threadIdx.x; idx < n; idx += blockDim.x){
                int ixj = idx ^ j;
                if (ixj > idx){
                    unsigned x = a[idx], y = a[ixj];
                    bool sw = ((idx & k) == 0) ? (x > y) : (x < y);
                    if (sw){ a[idx] = y; a[ixj] = x; }
                }
            }
            __syncthreads();
        }
}

/* fast threshold find over NB bins (blockDim must be 512):
   largest t with suffix-count >= k; res[0]=t, res[1]=k - suffix(t+1).
   3 barriers via warp-shfl hierarchical suffix scan. */
__device__ void ft_fast(const unsigned* hist, int NB, int k,
                        unsigned* wtot, int* res){
    int tid = threadIdx.x, lane = tid & 31, wid = tid >> 5;
    int BPT = NB >> 9;
    int b0 = tid * BPT;
    unsigned s = 0;
    for (int q = 0; q < BPT; ++q) s += hist[b0 + q];
    unsigned suf = s;
    #pragma unroll
    for (int d = 1; d < 32; d <<= 1){
        unsigned v = __shfl_down_sync(0xFFFFFFFFu, suf, d);
        if (lane + d < 32) suf += v;
    }
    if (lane == 0) wtot[wid] = suf;
    __syncthreads();
    if (tid < 16){
        unsigned w = wtot[tid];
        #pragma unroll
        for (int d = 1; d < 16; d <<= 1){
            unsigned v = __shfl_down_sync(0xFFFFu, w, d);
            if (tid + d < 16) w += v;
        }
        wtot[tid] = w;               /* inclusive suffix over warps */
    }
    __syncthreads();
    unsigned above_w = (wid + 1 < 16) ? wtot[wid + 1] : 0u;
    unsigned c = above_w + (suf - s);   /* count strictly above my bin group */
    for (int q = BPT - 1; q >= 0; --q){
        unsigned h = hist[b0 + q];
        if (c < (unsigned)k && c + h >= (unsigned)k){ res[0] = b0 + q; res[1] = k - (int)c; }
        c += h;
    }
    __syncthreads();
}

/* ---------------- K1: fused candidate compaction (float4, static guess) ----------------
   NOTE: loop bound is warp-uniform (v0), all 32 lanes always reach the shuffles. */
__global__ __launch_bounds__(256) void cand_kernel(const float* __restrict__ obj){
    __shared__ int s_cnt;
    int lev = blockIdx.x, b = blockIdx.y, ch = blockIdx.z, tid = threadIdx.x;
    int cell = b*5 + lev;
    if (lev == 0 && b == 0 && ch == 0 && tid < BB) g_maxb[tid] = 0;
    int n = c_ln[lev];
    int chunk = n / CH1;               /* all levels divisible by CH1*4 */
    int s = ch * chunk;
    const float4* p4 = (const float4*)(obj + (size_t)b*ATOT + c_loff[lev] + s);
    int nv = chunk >> 2;
    unsigned G = c_guess[lev];
    int lane = tid & 31;
    if (tid == 0) s_cnt = 0;
    __syncthreads();
    for (int v0 = 0; v0 < nv; v0 += 256){
        int v = v0 + tid;
        bool in = (v < nv);
        unsigned long long lc[4]; int cnt = 0;
        if (in){
            float4 f = p4[v];
            unsigned u0 = fkey(f.x), u1 = fkey(f.y), u2 = fkey(f.z), u3 = fkey(f.w);
            int i0 = s + 4*v;
            if (u0 >= G) lc[cnt++] = pack_ki(u0, (unsigned)i0);
            if (u1 >= G) lc[cnt++] = pack_ki(u1, (unsigned)(i0+1));
            if (u2 >= G) lc[cnt++] = pack_ki(u2, (unsigned)(i0+2));
            if (u3 >= G) lc[cnt++] = pack_ki(u3, (unsigned)(i0+3));
        }
        int incl = cnt;
        #pragma unroll
        for (int d = 1; d < 32; d <<= 1){
            int t = __shfl_up_sync(0xFFFFFFFFu, incl, d);
            if (lane >= d) incl += t;
        }
        int wtotal = __shfl_sync(0xFFFFFFFFu, incl, 31);
        int base = 0;
        if (lane == 31 && wtotal) base = atomicAdd(&s_cnt, wtotal);
        base = __shfl_sync(0xFFFFFFFFu, base, 31);
        int off = base + incl - cnt;
        for (int q = 0; q < cnt; ++q){
            int slot = off + q;
            if (slot < CHCAP) g_cand[cell][ch*CHCAP + slot] = lc[q];
        }
    }
    __syncthreads();
    if (tid == 0) g_ccnt[cell][ch] = s_cnt;
}

/* ---------------- K2: exact top-k over candidates + fused decode ---------------- */
__global__ __launch_bounds__(512) void select_kernel(const float* __restrict__ obj,
                                                     const float* __restrict__ deltas,
                                                     const float* __restrict__ anchors){
    extern __shared__ unsigned char dsm[];
    unsigned long long* scand = (unsigned long long*)dsm;       /* SCAP */
    unsigned long long* sel   = scand + SCAP;                   /* 1024 */
    unsigned* hist = (unsigned*)(sel + 1024);                   /* 2048 */
    unsigned* ties = hist + 2048;                               /* 1024 */
    __shared__ unsigned wtot[16];
    __shared__ int res2[2];
    __shared__ int co[CH1+1];
    __shared__ int s_ngt, s_neq, s_fb, s_max;

    int lev = blockIdx.x, b = blockIdx.y, tid = threadIdx.x, lane = tid & 31;
    int cell = b*5 + lev;
    int n = c_ln[lev], k = c_lk[lev];
    const float* p = obj + (size_t)b*ATOT + c_loff[lev];

    if (tid == 0){
        int acc = 0, of = 0;
        for (int ch = 0; ch < CH1; ++ch){
            co[ch] = acc;
            int cc = g_ccnt[cell][ch];
            if (cc > CHCAP){ of = 1; cc = CHCAP; }
            acc += cc;
        }
        co[CH1] = acc;
        s_fb = (of || acc < k);
        s_ngt = 0; s_neq = 0; s_max = 0;
    }
    __syncthreads();
    int fb = s_fb;
    int nc = co[CH1];

    for (int i = tid; i < 2048; i += 512) hist[i] = 0;
    if (!fb){
        for (int ch = 0; ch < CH1; ++ch){
            int c0 = co[ch], cc = co[ch+1] - c0;
            for (int i = tid; i < cc; i += 512) scand[c0 + i] = g_cand[cell][ch*CHCAP + i];
        }
    }
    __syncthreads();

    /* pass 1: top 11 bits */
    if (!fb){
        for (int base = 0; base < nc; base += 512){
            int i = base + tid;
            unsigned bin = 0xFFFFFFFFu;
            if (i < nc) bin = (unsigned)(scand[i] >> 32) >> 21;
            unsigned mm = __match_any_sync(0xFFFFFFFFu, bin);
            if (bin != 0xFFFFFFFFu && lane == (__ffs(mm)-1)) atomicAdd(&hist[bin], __popc(mm));
        }
    } else {
        for (int base = 0; base < n; base += 512){
            int i = base + tid;
            unsigned bin = 0xFFFFFFFFu;
            if (i < n) bin = fkey(p[i]) >> 21;
            unsigned mm = __match_any_sync(0xFFFFFFFFu, bin);
            if (bin != 0xFFFFFFFFu && lane == (__ffs(mm)-1)) atomicAdd(&hist[bin], __popc(mm));
        }
    }
    __syncthreads();
    ft_fast(hist, 2048, k, wtot, res2);
    unsigned t1 = (unsigned)res2[0]; int k1 = res2[1];
    for (int i = tid; i < 2048; i += 512) hist[i] = 0;
    __syncthreads();

    /* pass 2: mid 11 bits among bin==t1; collect strictly-above bins */
    if (!fb){
        for (int base = 0; base < nc; base += 512){
            int i = base + tid;
            unsigned bin = 0xFFFFFFFFu;
            if (i < nc){
                unsigned long long cv = scand[i];
                unsigned u = (unsigned)(cv >> 32);
                unsigned b31 = u >> 21;
                if (b31 > t1){ int q = atomicAdd(&s_ngt, 1); sel[q] = cv; }
                else if (b31 == t1) bin = (u >> 10) & 0x7FFu;
            }
            unsigned mm = __match_any_sync(0xFFFFFFFFu, bin);
            if (bin != 0xFFFFFFFFu && lane == (__ffs(mm)-1)) atomicAdd(&hist[bin], __popc(mm));
        }
    } else {
        for (int base = 0; base < n; base += 512){
            int i = base + tid;
            unsigned bin = 0xFFFFFFFFu;
            if (i < n){
                unsigned u = fkey(p[i]);
                unsigned b31 = u >> 21;
                if (b31 > t1){ int q = atomicAdd(&s_ngt, 1); sel[q] = pack_ki(u, (unsigned)i); }
                else if (b31 == t1) bin = (u >> 10) & 0x7FFu;
            }
            unsigned mm = __match_any_sync(0xFFFFFFFFu, bin);
            if (bin != 0xFFFFFFFFu && lane == (__ffs(mm)-1)) atomicAdd(&hist[bin], __popc(mm));
        }
    }
    __syncthreads();
    ft_fast(hist, 2048, k1, wtot, res2);
    unsigned t2 = (unsigned)res2[0]; int k2 = res2[1];
    unsigned pre22 = (t1 << 11) | t2;
    for (int i = tid; i < 1024; i += 512) hist[i] = 0;
    __syncthreads();

    /* pass 3: low 10 bits among 22-bit prefix match */
    if (!fb){
        for (int base = 0; base < nc; base += 512){
            int i = base + tid;
            unsigned bin = 0xFFFFFFFFu;
            if (i < nc){
                unsigned u = (unsigned)(scand[i] >> 32);
                if ((u >> 10) == pre22) bin = u & 0x3FFu;
            }
            unsigned mm = __match_any_sync(0xFFFFFFFFu, bin);
            if (bin != 0xFFFFFFFFu && lane == (__ffs(mm)-1)) atomicAdd(&hist[bin], __popc(mm));
        }
    } else {
        for (int base = 0; base < n; base += 512){
            int i = base + tid;
            unsigned bin = 0xFFFFFFFFu;
            if (i < n){
                unsigned u = fkey(p[i]);
                if ((u >> 10) == pre22) bin = u & 0x3FFu;
            }
            unsigned mm = __match_any_sync(0xFFFFFFFFu, bin);
            if (bin != 0xFFFFFFFFu && lane == (__ffs(mm)-1)) atomicAdd(&hist[bin], __popc(mm));
        }
    }
    __syncthreads();
    ft_fast(hist, 1024, k2, wtot, res2);
    unsigned T = (pre22 << 10) | (unsigned)res2[0];
    int rem = res2[1];

    /* collect remaining strictly-above (prefix==t1) + ties at T */
    if (!fb){
        for (int i = tid; i < nc; i += 512){
            unsigned long long cv = scand[i];
            unsigned u = (unsigned)(cv >> 32);
            if ((u >> 21) == t1){
                if (u > T){ int q = atomicAdd(&s_ngt, 1); sel[q] = cv; }
                else if (u == T){
                    int q = atomicAdd(&s_neq, 1);
                    if (q < 1024) ties[q] = 0xFFFFFFFFu - (unsigned)(cv & 0xFFFFFFFFull);
                }
            }
        }
    } else {
        for (int i = tid; i < n; i += 512){
            unsigned u = fkey(p[i]);
            if ((u >> 21) == t1){
                if (u > T){ int q = atomicAdd(&s_ngt, 1); sel[q] = pack_ki(u, (unsigned)i); }
                else if (u == T){
                    int q = atomicAdd(&s_neq, 1);
                    if (q < 1024) ties[q] = (unsigned)i;
                }
            }
        }
    }
    __syncthreads();
    int ngt = s_ngt, neq = min(s_neq, 1024);
    if (neq > rem){                    /* only then does tie order matter */
        for (int i = neq + tid; i < 1024; i += 512) ties[i] = 0xFFFFFFFFu;
        __syncthreads();
        bitonic_asc_u32(ties, 1024);
    }
    for (int r = tid; r < rem; r += 512)
        sel[ngt + r] = ((unsigned long long)T << 32) | (unsigned long long)(0xFFFFFFFFu - ties[r]);
    for (int r = k + tid; r < 1024; r += 512) sel[r] = 0ull;
    __syncthreads();
    bitonic_desc_u64(sel, 1024);       /* (value desc, idx asc) = lax.top_k order */

    /* fused decode + clip + score + validity + per-image max */
    int koff = c_lkoff[lev], off = c_loff[lev];
    float lmax = 0.f;
    for (int r = tid; r < k; r += 512){
        unsigned long long cc = sel[r];
        unsigned u = (unsigned)(cc >> 32);
        unsigned li = 0xFFFFFFFFu - (unsigned)(cc & 0xFFFFFFFFull);
        int a = off + (int)li;
        float4 an = ((const float4*)anchors)[a];
        float4 d  = ((const float4*)deltas)[(size_t)b*ATOT + a];
        float wa = an.z - an.x, ha = an.w - an.y;
        float cxa = an.x + 0.5f*wa, cya = an.y + 0.5f*ha;
        float dw = fminf(d.z, BXC), dh = fminf(d.w, BXC);
        float pcx = d.x*wa + cxa, pcy = d.y*ha + cya;
        float pw = expf(dw)*wa, ph = expf(dh)*ha;
        float x1 = pcx - 0.5f*pw, y1 = pcy - 0.5f*ph;
        float x2 = pcx + 0.5f*pw, y2 = pcy + 0.5f*ph;
        x1 = fminf(fmaxf(x1, 0.f), 1024.f);
        y1 = fminf(fmaxf(y1, 0.f), 768.f);
        x2 = fminf(fmaxf(x2, 0.f), 1024.f);
        y2 = fminf(fmaxf(y2, 0.f), 768.f);
        /* recover raw objectness from key (exact inverse of fkey) */
        unsigned xb = (u & 0x80000000u) ? (u & 0x7FFFFFFFu) : ~u;
        float xo = __uint_as_float(xb);
        float sc = 1.f/(1.f + expf(-xo));
        int v = ((x2 - x1) >= 1.0f) && ((y2 - y1) >= 1.0f) && (sc >= 0.f);
        int e = b*KTOT + koff + r;
        g_boxes[e]  = make_float4(x1, y1, x2, y2);
        g_scores[e] = sc;
        g_valid[e]  = v;
        lmax = fmaxf(lmax, fmaxf(fmaxf(x1, y1), fmaxf(x2, y2)));
    }
    atomicMax(&s_max, __float_as_int(lmax));   /* coords >= 0 -> int compare safe */
    __syncthreads();
    if (tid == 0) atomicMax(&g_maxb[b], s_max);
}

/* ---------------- K3a: NMS suppression matrix (triangular, row-strided) ---------------- */
__global__ __launch_bounds__(128) void nmsA_kernel(){
    __shared__ float sx1[1024], sy1[1024], sx2[1024], sy2[1024], sar[1024];
    int lev = blockIdx.x, b = blockIdx.y, z = blockIdx.z, tid = threadIdx.x;
    int cell = b*5 + lev;
    int m = c_lk[lev];
    int base = b*KTOT + c_lkoff[lev];
    float c = (float)lev * (__int_as_float(g_maxb[b]) + 1.0f);
    for (int i = tid; i < m; i += 128){
        float4 bx = g_boxes[base + i];
        float nx1 = bx.x + c, ny1 = bx.y + c, nx2 = bx.z + c, ny2 = bx.w + c;
        sx1[i] = nx1; sy1[i] = ny1; sx2[i] = nx2; sy2[i] = ny2;
        sar[i] = (nx2 - nx1)*(ny2 - ny1);
    }
    __syncthreads();
    for (int i = z + 8*tid; i < m; i += 1024){
        float ax1 = sx1[i], ay1 = sy1[i], ax2 = sx2[i], ay2 = sy2[i], aa = sar[i];
        unsigned long long wr[ROWW];
        unsigned long long any = 0ull;
        #pragma unroll
        for (int w = 0; w < ROWW; ++w){
            int j0 = w << 6;
            unsigned long long bits = 0ull;
            int jend = min(j0 + 64, m);
            int jstart = max(j0, i + 1);
            for (int j = jstart; j < jend; ++j){
                float iw = fmaxf(fminf(ax2, sx2[j]) - fmaxf(ax1, sx1[j]), 0.f);
                float ih = fmaxf(fminf(ay2, sy2[j]) - fmaxf(ay1, sy1[j]), 0.f);
                float inter = iw*ih;
                /* iou > 0.7 <=> inter > 0.7*union */
                if (inter > 0.7f*(aa + sar[j] - inter)) bits |= (1ull << (j - j0));
            }
            wr[w] = bits; any |= bits;
        }
        g_suprow[cell][i] = any ? 1 : 0;
        if (any){
            #pragma unroll
            for (int w = 0; w < ROWW; ++w) g_mat2[cell][i][w] = wr[w];
        }
    }
}

/* ---------------- K3b: serial greedy over suppressor rows only ---------------- */
__global__ __launch_bounds__(512) void nmsB_kernel(){
    extern __shared__ unsigned long long mat[];   /* 1024 x ROWW */
    __shared__ unsigned long long keepw[ROWW], smask[ROWW];
    __shared__ unsigned kb32[32], sb32[32];
    int lev = blockIdx.x, b = blockIdx.y, tid = threadIdx.x;
    int cell = b*5 + lev;
    int m = c_lk[lev];
    int base = b*KTOT + c_lkoff[lev];
    for (int i = tid; i < 1024; i += 512){
        int pk = (i < m) && g_valid[base + i];
        int ps = (i < m) && g_suprow[cell][i];
        unsigned bk = __ballot_sync(0xFFFFFFFFu, pk);
        unsigned bs = __ballot_sync(0xFFFFFFFFu, ps);
        if ((tid & 31) == 0){ kb32[i >> 5] = bk; sb32[i >> 5] = bs; }
    }
    __syncthreads();
    if (tid < ROWW){
        keepw[tid] = ((unsigned long long)kb32[2*tid + 1] << 32) | (unsigned long long)kb32[2*tid];
        smask[tid] = ((unsigned long long)sb32[2*tid + 1] << 32) | (unsigned long long)sb32[2*tid];
    }
    __syncthreads();
    for (int t = tid; t < 1024*ROWW; t += 512){
        int i = t >> 4, w = t & (ROWW - 1);
        if ((smask[i >> 6] >> (i & 63)) & 1ull) mat[t] = g_mat2[cell][i][w];
    }
    __syncthreads();
    if (tid < 32){
        for (int w16 = 0; w16 < ROWW; ++w16){
            unsigned long long mw = smask[w16];
            while (mw){
                int bpos = __ffsll((long long)mw) - 1;
                mw &= mw - 1ull;
                int i = (w16 << 6) + bpos;
                if ((keepw[i >> 6] >> (i & 63)) & 1ull){
                    if (tid < ROWW) keepw[tid] &= ~mat[i*ROWW + tid];
                }
                __syncwarp();
            }
        }
    }
    __syncthreads();
    for (int i = tid; i < m; i += 512)
        g_keep[base + i] = (int)((keepw[i >> 6] >> (i & 63)) & 1ull);
}

/* ---------------- K4: per-image post-NMS top-1000 via radix select + 1024 sort ------------- */
__global__ __launch_bounds__(512) void final_kernel(float* __restrict__ out){
    __shared__ unsigned skey[KTOT];
    __shared__ unsigned hist[2048];
    __shared__ unsigned long long sel[1024];
    __shared__ unsigned ties[1024];
    __shared__ unsigned wtot[16];
    __shared__ int res2[2];
    __shared__ int s_ngt, s_neq;

    int b = blockIdx.x, tid = threadIdx.x, lane = tid & 31;
    const int K2 = 1000;

    for (int i = tid; i < KTOT; i += 512){
        unsigned kk = 0u;
        if (g_keep[b*KTOT + i]) kk = __float_as_uint(g_scores[b*KTOT + i]) | 0x80000000u;
        skey[i] = kk;
    }
    for (int i = tid; i < 2048; i += 512) hist[i] = 0;
    if (tid == 0){ s_ngt = 0; s_neq = 0; }
    __syncthreads();
    for (int base = 0; base < KTOT; base += 512){
        int i = base + tid;
        unsigned bin = 0xFFFFFFFFu;
        if (i < KTOT) bin = skey[i] >> 21;
        unsigned mm = __match_any_sync(0xFFFFFFFFu, bin);
        if (bin != 0xFFFFFFFFu && lane == (__ffs(mm)-1)) atomicAdd(&hist[bin], __popc(mm));
    }
    __syncthreads();
    ft_fast(hist, 2048, K2, wtot, res2);
    unsigned t1 = (unsigned)res2[0]; int k1 = res2[1];
    for (int i = tid; i < 2048; i += 512) hist[i] = 0;
    __syncthreads();
    for (int base = 0; base < KTOT; base += 512){
        int i = base + tid;
        unsigned bin = 0xFFFFFFFFu;
        if (i < KTOT){
            unsigned u = skey[i];
            unsigned b31 = u >> 21;
            if (b31 > t1){ int q = atomicAdd(&s_ngt, 1); sel[q] = pack_ki(u, (unsigned)i); }
            else if (b31 == t1) bin = (u >> 10) & 0x7FFu;
        }
        unsigned mm = __match_any_sync(0xFFFFFFFFu, bin);
        if (bin != 0xFFFFFFFFu && lane == (__ffs(mm)-1)) atomicAdd(&hist[bin], __popc(mm));
    }
    __syncthreads();
    ft_fast(hist, 2048, k1, wtot, res2);
    unsigned t2 = (unsigned)res2[0]; int k2 = res2[1];
    unsigned pre22 = (t1 << 11) | t2;
    for (int i = tid; i < 1024; i += 512) hist[i] = 0;
    __syncthreads();
    for (int base = 0; base < KTOT; base += 512){
        int i = base + tid;
        unsigned bin = 0xFFFFFFFFu;
        if (i < KTOT){
            unsigned u = skey[i];
            if ((u >> 10) == pre22) bin = u & 0x3FFu;
        }
        unsigned mm = __match_any_sync(0xFFFFFFFFu, bin);
        if (bin != 0xFFFFFFFFu && lane == (__ffs(mm)-1)) atomicAdd(&hist[bin], __popc(mm));
    }
    __syncthreads();
    ft_fast(hist, 1024, k2, wtot, res2);
    unsigned T = (pre22 << 10) | (unsigned)res2[0];
    int rem = res2[1];
    for (int i = tid; i < KTOT; i += 512){
        unsigned u = skey[i];
        if ((u >> 21) == t1){
            if (u > T){ int q = atomicAdd(&s_ngt, 1); sel[q] = pack_ki(u, (unsigned)i); }
            else if (u == T){
                int q = atomicAdd(&s_neq, 1);
                if (q < 1024) ties[q] = (unsigned)i;
            }
        }
    }
    __syncthreads();
    int ngt = s_ngt, neq = min(s_neq, 1024);
    if (neq > rem){
        for (int i = neq + tid; i < 1024; i += 512) ties[i] = 0xFFFFFFFFu;
        __syncthreads();
        bitonic_asc_u32(ties, 1024);
    }
    for (int r = tid; r < rem; r += 512)
        sel[ngt + r] = ((unsigned long long)T << 32) | (unsigned long long)(0xFFFFFFFFu - ties[r]);
    for (int r = K2 + tid; r < 1024; r += 512) sel[r] = 0ull;
    __syncthreads();
    bitonic_desc_u64(sel, 1024);
    for (int r = tid; r < K2; r += 512){
        unsigned long long cc = sel[r];
        float* o = out + ((size_t)b*1000 + r)*5;
        if ((unsigned)(cc >> 32) & 0x80000000u){   /* kept keys always have bit31 set */
            int pos = (int)(0xFFFFFFFFu - (unsigned)(cc & 0xFFFFFFFFull));
            float4 bx = g_boxes[b*KTOT + pos];
            o[0] = bx.x; o[1] = bx.y; o[2] = bx.z; o[3] = bx.w;
            o[4] = g_scores[b*KTOT + pos];
        } else {
            o[0] = 0.f; o[1] = 0.f; o[2] = 0.f; o[3] = 0.f; o[4] = 0.f;
        }
    }
}

extern "C" void kernel_launch(void* const* d_in, const int* in_sizes, int n_in,
                              void* d_out, int out_size){
    const float* obj     = (const float*)d_in[0];
    const float* deltas  = (const float*)d_in[1];
    const float* anchors = (const float*)d_in[2];
    float* out = (float*)d_out;

    const int DSM_SEL = SCAP*8 + 1024*8 + 2048*4 + 1024*4;  /* 86016  */
    const int DSM_B   = 1024*ROWW*8;                         /* 131072 */
    cudaFuncSetAttribute(select_kernel, cudaFuncAttributeMaxDynamicSharedMemorySize, DSM_SEL);
    cudaFuncSetAttribute(nmsB_kernel,   cudaFuncAttributeMaxDynamicSharedMemorySize, DSM_B);

    cand_kernel  <<<dim3(5, BB, CH1), 256>>>(obj);
    select_kernel<<<dim3(5, BB), 512, DSM_SEL>>>(obj, deltas, anchors);
    nmsA_kernel  <<<dim3(5, BB, 8), 128>>>();
    nmsB_kernel  <<<dim3(5, BB), 512, DSM_B>>>();
    final_kernel <<<BB, 512>>>(out);
}

// round 13
// speedup vs baseline: 9.0909x; 1.0136x over previous
#include <cuda_runtime.h>

#define BB    8
#define ATOT  196416
#define KTOT  4576
#define BXC   4.135166556742356f   /* log(1000/16) */
#define ROWW  16
#define CH1   16
#define CHCAP 512
#define SCAP  (CH1*CHCAP)          /* 8192 */
#define NCELL 40

__constant__ int c_ln[5]    = {147456,36864,9216,2304,576};
__constant__ int c_loff[5]  = {0,147456,184320,193536,195840};
__constant__ int c_lk[5]    = {1000,1000,1000,1000,576};
__constant__ int c_lkoff[5] = {0,1000,2000,3000,4000};
/* static candidate guesses: fkey(2.0), fkey(1.5), fkey(0.5), take-all, take-all */
__constant__ unsigned c_guess[5] = {0xC0000000u, 0xBFC00000u, 0xBF000000u, 0u, 0u};

__device__ unsigned long long g_cand[NCELL][SCAP];
__device__ int                g_ccnt[NCELL][CH1];
__device__ unsigned long long g_mat2[NCELL][1024][ROWW];
__device__ int                g_suprow2[NCELL][2][1024];
__device__ float4 g_boxes [BB*KTOT];
__device__ float  g_scores[BB*KTOT];
__device__ int    g_valid [BB*KTOT];
__device__ int    g_keep  [BB*KTOT];
__device__ int    g_maxb  [BB];

__device__ __forceinline__ unsigned fkey(float f){
    unsigned u = __float_as_uint(f);
    return (u & 0x80000000u) ? ~u : (u | 0x80000000u);
}
__device__ __forceinline__ unsigned long long pack_ki(unsigned u, unsigned i){
    return ((unsigned long long)u << 32) | (unsigned long long)(0xFFFFFFFFu - i);
}

/* bitonic sorts, blockDim 512, n=1024 (each thread owns idx=tid and idx=tid+512).
   Stages with j<=16 are warp-confined -> __syncwarp unless adjacent stage crosses warps. */
__device__ void bitonic_desc_u64(unsigned long long* a, int n){
    for (int k = 2; k <= n; k <<= 1)
        for (int j = k >> 1; j > 0; j >>= 1){
            for (int idx = threadIdx.x; idx < n; idx += blockDim.x){
                int ixj = idx ^ j;
                if (ixj > idx){
                    unsigned long long x = a[idx], y = a[ixj];
                    bool sw = ((idx & k) == 0) ? (x < y) : (x > y);
                    if (sw){ a[idx] = y; a[ixj] = x; }
                }
            }
            int jn = (j > 1) ? (j >> 1) : k;   /* next stage's j (next k starts at j=k) */
            if (j > 16 || jn > 16) __syncthreads(); else __syncwarp();
        }
}
__device__ void bitonic_asc_u32(unsigned* a, int n){
    for (int k = 2; k <= n; k <<= 1)
        for (int j = k >> 1; j > 0; j >>= 1){
            for (int idx = threadIdx.x; idx < n; idx += blockDim.x){
                int ixj = idx ^ j;
                if (ixj > idx){
                    unsigned x = a[idx], y = a[ixj];
                    bool sw = ((idx & k) == 0) ? (x > y) : (x < y);
                    if (sw){ a[idx] = y; a[ixj] = x; }
                }
            }
            int jn = (j > 1) ? (j >> 1) : k;
            if (j > 16 || jn > 16) __syncthreads(); else __syncwarp();
        }
}

/* fast threshold find over NB bins (blockDim must be 512):
   largest t with suffix-count >= k; res[0]=t, res[1]=k - suffix(t+1). */
__device__ void ft_fast(const unsigned* hist, int NB, int k,
                        unsigned* wtot, int* res){
    int tid = threadIdx.x, lane = tid & 31, wid = tid >> 5;
    int BPT = NB >> 9;
    int b0 = tid * BPT;
    unsigned s = 0;
    for (int q = 0; q < BPT; ++q) s += hist[b0 + q];
    unsigned suf = s;
    #pragma unroll
    for (int d = 1; d < 32; d <<= 1){
        unsigned v = __shfl_down_sync(0xFFFFFFFFu, suf, d);
        if (lane + d < 32) suf += v;
    }
    if (lane == 0) wtot[wid] = suf;
    __syncthreads();
    if (tid < 16){
        unsigned w = wtot[tid];
        #pragma unroll
        for (int d = 1; d < 16; d <<= 1){
            unsigned v = __shfl_down_sync(0xFFFFu, w, d);
            if (tid + d < 16) w += v;
        }
        wtot[tid] = w;
    }
    __syncthreads();
    unsigned above_w = (wid + 1 < 16) ? wtot[wid + 1] : 0u;
    unsigned c = above_w + (suf - s);
    for (int q = BPT - 1; q >= 0; --q){
        unsigned h = hist[b0 + q];
        if (c < (unsigned)k && c + h >= (unsigned)k){ res[0] = b0 + q; res[1] = k - (int)c; }
        c += h;
    }
    __syncthreads();
}

/* ---------------- K1: fused candidate compaction (2x float4 per thread) ---------------- */
__global__ __launch_bounds__(256) void cand_kernel(const float* __restrict__ obj){
    __shared__ int s_cnt;
    int lev = blockIdx.x, b = blockIdx.y, ch = blockIdx.z, tid = threadIdx.x;
    int cell = b*5 + lev;
    if (lev == 0 && b == 0 && ch == 0 && tid < BB) g_maxb[tid] = 0;
    int n = c_ln[lev];
    int chunk = n / CH1;
    int s = ch * chunk;
    const float4* p4 = (const float4*)(obj + (size_t)b*ATOT + c_loff[lev] + s);
    int nv = chunk >> 2;
    unsigned G = c_guess[lev];
    int lane = tid & 31;
    if (tid == 0) s_cnt = 0;
    __syncthreads();
    for (int v0 = 0; v0 < nv; v0 += 512){      /* warp-uniform bound */
        int va = v0 + tid, vb = v0 + 256 + tid;
        unsigned long long lc[8]; int cnt = 0;
        if (va < nv){
            float4 f = p4[va];
            unsigned u0 = fkey(f.x), u1 = fkey(f.y), u2 = fkey(f.z), u3 = fkey(f.w);
            int i0 = s + 4*va;
            if (u0 >= G) lc[cnt++] = pack_ki(u0, (unsigned)i0);
            if (u1 >= G) lc[cnt++] = pack_ki(u1, (unsigned)(i0+1));
            if (u2 >= G) lc[cnt++] = pack_ki(u2, (unsigned)(i0+2));
            if (u3 >= G) lc[cnt++] = pack_ki(u3, (unsigned)(i0+3));
        }
        if (vb < nv){
            float4 f = p4[vb];
            unsigned u0 = fkey(f.x), u1 = fkey(f.y), u2 = fkey(f.z), u3 = fkey(f.w);
            int i0 = s + 4*vb;
            if (u0 >= G) lc[cnt++] = pack_ki(u0, (unsigned)i0);
            if (u1 >= G) lc[cnt++] = pack_ki(u1, (unsigned)(i0+1));
            if (u2 >= G) lc[cnt++] = pack_ki(u2, (unsigned)(i0+2));
            if (u3 >= G) lc[cnt++] = pack_ki(u3, (unsigned)(i0+3));
        }
        int incl = cnt;
        #pragma unroll
        for (int d = 1; d < 32; d <<= 1){
            int t = __shfl_up_sync(0xFFFFFFFFu, incl, d);
            if (lane >= d) incl += t;
        }
        int wtotal = __shfl_sync(0xFFFFFFFFu, incl, 31);
        int base = 0;
        if (lane == 31 && wtotal) base = atomicAdd(&s_cnt, wtotal);
        base = __shfl_sync(0xFFFFFFFFu, base, 31);
        int off = base + incl - cnt;
        for (int q = 0; q < cnt; ++q){
            int slot = off + q;
            if (slot < CHCAP) g_cand[cell][ch*CHCAP + slot] = lc[q];
        }
    }
    __syncthreads();
    if (tid == 0) g_ccnt[cell][ch] = s_cnt;
}

/* NOTE: candidate order within a chunk is NOT index-sorted, but selection is order-
   independent and final ordering comes from the u64 bitonic sort (key has idx packed). */

/* ---------------- K2: exact top-k over candidates + fused decode ---------------- */
__global__ __launch_bounds__(512) void select_kernel(const float* __restrict__ obj,
                                                     const float* __restrict__ deltas,
                                                     const float* __restrict__ anchors){
    extern __shared__ unsigned char dsm[];
    unsigned long long* scand = (unsigned long long*)dsm;       /* SCAP */
    unsigned long long* sel   = scand + SCAP;                   /* 1024 */
    unsigned* hist = (unsigned*)(sel + 1024);                   /* 2048 */
    unsigned* ties = hist + 2048;                               /* 1024 */
    __shared__ unsigned wtot[16];
    __shared__ int res2[2];
    __shared__ int co[CH1+1];
    __shared__ int s_ngt, s_neq, s_fb, s_max;

    int lev = blockIdx.x, b = blockIdx.y, tid = threadIdx.x, lane = tid & 31;
    int cell = b*5 + lev;
    int n = c_ln[lev], k = c_lk[lev];
    const float* p = obj + (size_t)b*ATOT + c_loff[lev];

    if (tid == 0){
        int acc = 0, of = 0;
        for (int ch = 0; ch < CH1; ++ch){
            co[ch] = acc;
            int cc = g_ccnt[cell][ch];
            if (cc > CHCAP){ of = 1; cc = CHCAP; }
            acc += cc;
        }
        co[CH1] = acc;
        s_fb = (of || acc < k);
        s_ngt = 0; s_neq = 0; s_max = 0;
    }
    __syncthreads();
    int fb = s_fb;
    int nc = co[CH1];

    for (int i = tid; i < 2048; i += 512) hist[i] = 0;
    if (!fb){
        for (int ch = 0; ch < CH1; ++ch){
            int c0 = co[ch], cc = co[ch+1] - c0;
            for (int i = tid; i < cc; i += 512) scand[c0 + i] = g_cand[cell][ch*CHCAP + i];
        }
    }
    __syncthreads();

    /* pass 1: top 11 bits */
    if (!fb){
        for (int base = 0; base < nc; base += 512){
            int i = base + tid;
            unsigned bin = 0xFFFFFFFFu;
            if (i < nc) bin = (unsigned)(scand[i] >> 32) >> 21;
            unsigned mm = __match_any_sync(0xFFFFFFFFu, bin);
            if (bin != 0xFFFFFFFFu && lane == (__ffs(mm)-1)) atomicAdd(&hist[bin], __popc(mm));
        }
    } else {
        for (int base = 0; base < n; base += 512){
            int i = base + tid;
            unsigned bin = 0xFFFFFFFFu;
            if (i < n) bin = fkey(p[i]) >> 21;
            unsigned mm = __match_any_sync(0xFFFFFFFFu, bin);
            if (bin != 0xFFFFFFFFu && lane == (__ffs(mm)-1)) atomicAdd(&hist[bin], __popc(mm));
        }
    }
    __syncthreads();
    ft_fast(hist, 2048, k, wtot, res2);
    unsigned t1 = (unsigned)res2[0]; int k1 = res2[1];
    for (int i = tid; i < 2048; i += 512) hist[i] = 0;
    __syncthreads();

    /* pass 2 */
    if (!fb){
        for (int base = 0; base < nc; base += 512){
            int i = base + tid;
            unsigned bin = 0xFFFFFFFFu;
            if (i < nc){
                unsigned long long cv = scand[i];
                unsigned u = (unsigned)(cv >> 32);
                unsigned b31 = u >> 21;
                if (b31 > t1){ int q = atomicAdd(&s_ngt, 1); sel[q] = cv; }
                else if (b31 == t1) bin = (u >> 10) & 0x7FFu;
            }
            unsigned mm = __match_any_sync(0xFFFFFFFFu, bin);
            if (bin != 0xFFFFFFFFu && lane == (__ffs(mm)-1)) atomicAdd(&hist[bin], __popc(mm));
        }
    } else {
        for (int base = 0; base < n; base += 512){
            int i = base + tid;
            unsigned bin = 0xFFFFFFFFu;
            if (i < n){
                unsigned u = fkey(p[i]);
                unsigned b31 = u >> 21;
                if (b31 > t1){ int q = atomicAdd(&s_ngt, 1); sel[q] = pack_ki(u, (unsigned)i); }
                else if (b31 == t1) bin = (u >> 10) & 0x7FFu;
            }
            unsigned mm = __match_any_sync(0xFFFFFFFFu, bin);
            if (bin != 0xFFFFFFFFu && lane == (__ffs(mm)-1)) atomicAdd(&hist[bin], __popc(mm));
        }
    }
    __syncthreads();
    ft_fast(hist, 2048, k1, wtot, res2);
    unsigned t2 = (unsigned)res2[0]; int k2 = res2[1];
    unsigned pre22 = (t1 << 11) | t2;
    for (int i = tid; i < 1024; i += 512) hist[i] = 0;
    __syncthreads();

    /* pass 3 */
    if (!fb){
        for (int base = 0; base < nc; base += 512){
            int i = base + tid;
            unsigned bin = 0xFFFFFFFFu;
            if (i < nc){
                unsigned u = (unsigned)(scand[i] >> 32);
                if ((u >> 10) == pre22) bin = u & 0x3FFu;
            }
            unsigned mm = __match_any_sync(0xFFFFFFFFu, bin);
            if (bin != 0xFFFFFFFFu && lane == (__ffs(mm)-1)) atomicAdd(&hist[bin], __popc(mm));
        }
    } else {
        for (int base = 0; base < n; base += 512){
            int i = base + tid;
            unsigned bin = 0xFFFFFFFFu;
            if (i < n){
                unsigned u = fkey(p[i]);
                if ((u >> 10) == pre22) bin = u & 0x3FFu;
            }
            unsigned mm = __match_any_sync(0xFFFFFFFFu, bin);
            if (bin != 0xFFFFFFFFu && lane == (__ffs(mm)-1)) atomicAdd(&hist[bin], __popc(mm));
        }
    }
    __syncthreads();
    ft_fast(hist, 1024, k2, wtot, res2);
    unsigned T = (pre22 << 10) | (unsigned)res2[0];
    int rem = res2[1];

    /* collect remaining strictly-above + ties at T */
    if (!fb){
        for (int i = tid; i < nc; i += 512){
            unsigned long long cv = scand[i];
            unsigned u = (unsigned)(cv >> 32);
            if ((u >> 21) == t1){
                if (u > T){ int q = atomicAdd(&s_ngt, 1); sel[q] = cv; }
                else if (u == T){
                    int q = atomicAdd(&s_neq, 1);
                    if (q < 1024) ties[q] = 0xFFFFFFFFu - (unsigned)(cv & 0xFFFFFFFFull);
                }
            }
        }
    } else {
        for (int i = tid; i < n; i += 512){
            unsigned u = fkey(p[i]);
            if ((u >> 21) == t1){
                if (u > T){ int q = atomicAdd(&s_ngt, 1); sel[q] = pack_ki(u, (unsigned)i); }
                else if (u == T){
                    int q = atomicAdd(&s_neq, 1);
                    if (q < 1024) ties[q] = (unsigned)i;
                }
            }
        }
    }
    __syncthreads();
    int ngt = s_ngt, neq = min(s_neq, 1024);
    if (neq > rem){
        for (int i = neq + tid; i < 1024; i += 512) ties[i] = 0xFFFFFFFFu;
        __syncthreads();
        bitonic_asc_u32(ties, 1024);
        __syncthreads();
    }
    for (int r = tid; r < rem; r += 512)
        sel[ngt + r] = ((unsigned long long)T << 32) | (unsigned long long)(0xFFFFFFFFu - ties[r]);
    for (int r = k + tid; r < 1024; r += 512) sel[r] = 0ull;
    __syncthreads();
    bitonic_desc_u64(sel, 1024);
    __syncthreads();

    /* fused decode + clip + score + validity + per-image max */
    int koff = c_lkoff[lev], off = c_loff[lev];
    float lmax = 0.f;
    for (int r = tid; r < k; r += 512){
        unsigned long long cc = sel[r];
        unsigned u = (unsigned)(cc >> 32);
        unsigned li = 0xFFFFFFFFu - (unsigned)(cc & 0xFFFFFFFFull);
        int a = off + (int)li;
        float4 an = ((const float4*)anchors)[a];
        float4 d  = ((const float4*)deltas)[(size_t)b*ATOT + a];
        float wa = an.z - an.x, ha = an.w - an.y;
        float cxa = an.x + 0.5f*wa, cya = an.y + 0.5f*ha;
        float dw = fminf(d.z, BXC), dh = fminf(d.w, BXC);
        float pcx = d.x*wa + cxa, pcy = d.y*ha + cya;
        float pw = expf(dw)*wa, ph = expf(dh)*ha;
        float x1 = pcx - 0.5f*pw, y1 = pcy - 0.5f*ph;
        float x2 = pcx + 0.5f*pw, y2 = pcy + 0.5f*ph;
        x1 = fminf(fmaxf(x1, 0.f), 1024.f);
        y1 = fminf(fmaxf(y1, 0.f), 768.f);
        x2 = fminf(fmaxf(x2, 0.f), 1024.f);
        y2 = fminf(fmaxf(y2, 0.f), 768.f);
        unsigned xb = (u & 0x80000000u) ? (u & 0x7FFFFFFFu) : ~u;
        float xo = __uint_as_float(xb);
        float sc = 1.f/(1.f + expf(-xo));
        int v = ((x2 - x1) >= 1.0f) && ((y2 - y1) >= 1.0f) && (sc >= 0.f);
        int e = b*KTOT + koff + r;
        g_boxes[e]  = make_float4(x1, y1, x2, y2);
        g_scores[e] = sc;
        g_valid[e]  = v;
        lmax = fmaxf(lmax, fmaxf(fmaxf(x1, y1), fmaxf(x2, y2)));
    }
    atomicMax(&s_max, __float_as_int(lmax));
    __syncthreads();
    if (tid == 0) atomicMax(&g_maxb[b], s_max);
}

/* ---------------- K3a: NMS suppression matrix (triangular, row+word-split) ---------------- */
__global__ __launch_bounds__(128) void nmsA_kernel(){
    __shared__ float sx1[1024], sy1[1024], sx2[1024], sy2[1024], sar[1024];
    int lev = blockIdx.x, b = blockIdx.y, z = blockIdx.z, tid = threadIdx.x;
    int cell = b*5 + lev;
    int m = c_lk[lev];
    int base = b*KTOT + c_lkoff[lev];
    int zr = z >> 1, half = z & 1;
    float c = (float)lev * (__int_as_float(g_maxb[b]) + 1.0f);
    for (int i = tid; i < m; i += 128){
        float4 bx = g_boxes[base + i];
        float nx1 = bx.x + c, ny1 = bx.y + c, nx2 = bx.z + c, ny2 = bx.w + c;
        sx1[i] = nx1; sy1[i] = ny1; sx2[i] = nx2; sy2[i] = ny2;
        sar[i] = (nx2 - nx1)*(ny2 - ny1);
    }
    __syncthreads();
    int w0 = half * 8;
    for (int i = zr + 8*tid; i < m; i += 1024){
        float ax1 = sx1[i], ay1 = sy1[i], ax2 = sx2[i], ay2 = sy2[i], aa = sar[i];
        unsigned long long wr[8];
        unsigned long long any = 0ull;
        #pragma unroll
        for (int ww = 0; ww < 8; ++ww){
            int w = w0 + ww;
            int j0 = w << 6;
            unsigned long long bits = 0ull;
            int jend = min(j0 + 64, m);
            int jstart = max(j0, i + 1);
            for (int j = jstart; j < jend; ++j){
                float iw = fmaxf(fminf(ax2, sx2[j]) - fmaxf(ax1, sx1[j]), 0.f);
                float ih = fmaxf(fminf(ay2, sy2[j]) - fmaxf(ay1, sy1[j]), 0.f);
                float inter = iw*ih;
                if (inter > 0.7f*(aa + sar[j] - inter)) bits |= (1ull << (j - j0));
            }
            wr[ww] = bits; any |= bits;
        }
        g_suprow2[cell][half][i] = any ? 1 : 0;   /* unconditional: deterministic, no init */
        if (any){
            #pragma unroll
            for (int ww = 0; ww < 8; ++ww) g_mat2[cell][i][w0 + ww] = wr[ww];
        }
    }
}

/* ---------------- K3b: serial greedy, register keep + pipelined mat prefetch ---------------- */
__global__ __launch_bounds__(512) void nmsB_kernel(){
    extern __shared__ unsigned long long mat[];   /* 1024 x ROWW */
    __shared__ unsigned long long keepw[ROWW];
    __shared__ unsigned kb32[32];
    __shared__ unsigned char sf0[1024], sf1[1024];
    __shared__ unsigned short slist[1024];
    int lev = blockIdx.x, b = blockIdx.y, tid = threadIdx.x, lane = tid & 31;
    int cell = b*5 + lev;
    int m = c_lk[lev];
    int base = b*KTOT + c_lkoff[lev];
    for (int i = tid; i < 1024; i += 512){
        int f0 = (i < m) ? g_suprow2[cell][0][i] : 0;
        int f1 = (i < m) ? g_suprow2[cell][1][i] : 0;
        sf0[i] = (unsigned char)f0; sf1[i] = (unsigned char)f1;
        int pk = (i < m) && g_valid[base + i];
        unsigned bk = __ballot_sync(0xFFFFFFFFu, pk);
        if (lane == 0) kb32[i >> 5] = bk;
    }
    __syncthreads();
    if (tid < ROWW)
        keepw[tid] = ((unsigned long long)kb32[2*tid + 1] << 32) | (unsigned long long)kb32[2*tid];
    /* load valid halves of suppressor rows; zero the other half */
    for (int t = tid; t < 1024*ROWW; t += 512){
        int i = t >> 4, w = t & (ROWW - 1);
        int f0 = sf0[i], f1 = sf1[i];
        if (f0 | f1)
            mat[t] = ((w < 8) ? f0 : f1) ? g_mat2[cell][i][w] : 0ull;
    }
    __syncthreads();
    if (tid < 32){
        /* ordered suppressor list via ballots */
        int ns = 0;
        for (int bse = 0; bse < 1024; bse += 32){
            int i = bse + lane;
            bool pr = (sf0[i] | sf1[i]) != 0;
            unsigned bl = __ballot_sync(0xFFFFFFFFu, pr);
            if (pr) slist[ns + __popc(bl & ((1u << lane) - 1))] = (unsigned short)i;
            ns += __popc(bl);
        }
        /* greedy: keep bits in lanes 0..15 registers; mat row prefetched */
        unsigned long long kreg = (lane < ROWW) ? keepw[lane] : 0ull;
        if (ns > 0){
            int icur = slist[0];
            unsigned long long mrow = (lane < ROWW) ? mat[icur*ROWW + lane] : 0ull;
            for (int s2 = 0; s2 < ns; ++s2){
                int inx = (s2 + 1 < ns) ? (int)slist[s2 + 1] : icur;
                unsigned long long mnext = (lane < ROWW) ? mat[inx*ROWW + lane] : 0ull;
                unsigned long long kw = __shfl_sync(0xFFFFFFFFu, kreg, icur >> 6);
                if ((kw >> (icur & 63)) & 1ull) kreg &= ~mrow;
                mrow = mnext; icur = inx;
            }
        }
        if (lane < ROWW) keepw[lane] = kreg;
    }
    __syncthreads();
    for (int i = tid; i < m; i += 512)
        g_keep[base + i] = (int)((keepw[i >> 6] >> (i & 63)) & 1ull);
}

/* ---------------- K4: per-image post-NMS top-1000 via radix select + 1024 sort ------------- */
__global__ __launch_bounds__(512) void final_kernel(float* __restrict__ out){
    __shared__ unsigned skey[KTOT];
    __shared__ unsigned hist[2048];
    __shared__ unsigned long long sel[1024];
    __shared__ unsigned ties[1024];
    __shared__ unsigned wtot[16];
    __shared__ int res2[2];
    __shared__ int s_ngt, s_neq;

    int b = blockIdx.x, tid = threadIdx.x, lane = tid & 31;
    const int K2 = 1000;

    for (int i = tid; i < KTOT; i += 512){
        unsigned kk = 0u;
        if (g_keep[b*KTOT + i]) kk = __float_as_uint(g_scores[b*KTOT + i]) | 0x80000000u;
        skey[i] = kk;
    }
    for (int i = tid; i < 2048; i += 512) hist[i] = 0;
    if (tid == 0){ s_ngt = 0; s_neq = 0; }
    __syncthreads();
    for (int base = 0; base < KTOT; base += 512){
        int i = base + tid;
        unsigned bin = 0xFFFFFFFFu;
        if (i < KTOT) bin = skey[i] >> 21;
        unsigned mm = __match_any_sync(0xFFFFFFFFu, bin);
        if (bin != 0xFFFFFFFFu && lane == (__ffs(mm)-1)) atomicAdd(&hist[bin], __popc(mm));
    }
    __syncthreads();
    ft_fast(hist, 2048, K2, wtot, res2);
    unsigned t1 = (unsigned)res2[0]; int k1 = res2[1];
    for (int i = tid; i < 2048; i += 512) hist[i] = 0;
    __syncthreads();
    for (int base = 0; base < KTOT; base += 512){
        int i = base + tid;
        unsigned bin = 0xFFFFFFFFu;
        if (i < KTOT){
            unsigned u = skey[i];
            unsigned b31 = u >> 21;
            if (b31 > t1){ int q = atomicAdd(&s_ngt, 1); sel[q] = pack_ki(u, (unsigned)i); }
            else if (b31 == t1) bin = (u >> 10) & 0x7FFu;
        }
        unsigned mm = __match_any_sync(0xFFFFFFFFu, bin);
        if (bin != 0xFFFFFFFFu && lane == (__ffs(mm)-1)) atomicAdd(&hist[bin], __popc(mm));
    }
    __syncthreads();
    ft_fast(hist, 2048, k1, wtot, res2);
    unsigned t2 = (unsigned)res2[0]; int k2 = res2[1];
    unsigned pre22 = (t1 << 11) | t2;
    for (int i = tid; i < 1024; i += 512) hist[i] = 0;
    __syncthreads();
    for (int base = 0; base < KTOT; base += 512){
        int i = base + tid;
        unsigned bin = 0xFFFFFFFFu;
        if (i < KTOT){
            unsigned u = skey[i];
            if ((u >> 10) == pre22) bin = u & 0x3FFu;
        }
        unsigned mm = __match_any_sync(0xFFFFFFFFu, bin);
        if (bin != 0xFFFFFFFFu && lane == (__ffs(mm)-1)) atomicAdd(&hist[bin], __popc(mm));
    }
    __syncthreads();
    ft_fast(hist, 1024, k2, wtot, res2);
    unsigned T = (pre22 << 10) | (unsigned)res2[0];
    int rem = res2[1];
    for (int i = tid; i < KTOT; i += 512){
        unsigned u = skey[i];
        if ((u >> 21) == t1){
            if (u > T){ int q = atomicAdd(&s_ngt, 1); sel[q] = pack_ki(u, (unsigned)i); }
            else if (u == T){
                int q = atomicAdd(&s_neq, 1);
                if (q < 1024) ties[q] = (unsigned)i;
            }
        }
    }
    __syncthreads();
    int ngt = s_ngt, neq = min(s_neq, 1024);
    if (neq > rem){
        for (int i = neq + tid; i < 1024; i += 512) ties[i] = 0xFFFFFFFFu;
        __syncthreads();
        bitonic_asc_u32(ties, 1024);
        __syncthreads();
    }
    for (int r = tid; r < rem; r += 512)
        sel[ngt + r] = ((unsigned long long)T << 32) | (unsigned long long)(0xFFFFFFFFu - ties[r]);
    for (int r = K2 + tid; r < 1024; r += 512) sel[r] = 0ull;
    __syncthreads();
    bitonic_desc_u64(sel, 1024);
    __syncthreads();
    for (int r = tid; r < K2; r += 512){
        unsigned long long cc = sel[r];
        float* o = out + ((size_t)b*1000 + r)*5;
        if ((unsigned)(cc >> 32) & 0x80000000u){
            int pos = (int)(0xFFFFFFFFu - (unsigned)(cc & 0xFFFFFFFFull));
            float4 bx = g_boxes[b*KTOT + pos];
            o[0] = bx.x; o[1] = bx.y; o[2] = bx.z; o[3] = bx.w;
            o[4] = g_scores[b*KTOT + pos];
        } else {
            o[0] = 0.f; o[1] = 0.f; o[2] = 0.f; o[3] = 0.f; o[4] = 0.f;
        }
    }
}

extern "C" void kernel_launch(void* const* d_in, const int* in_sizes, int n_in,
                              void* d_out, int out_size){
    const float* obj     = (const float*)d_in[0];
    const float* deltas  = (const float*)d_in[1];
    const float* anchors = (const float*)d_in[2];
    float* out = (float*)d_out;

    const int DSM_SEL = SCAP*8 + 1024*8 + 2048*4 + 1024*4;  /* 86016  */
    const int DSM_B   = 1024*ROWW*8;                         /* 131072 */
    cudaFuncSetAttribute(select_kernel, cudaFuncAttributeMaxDynamicSharedMemorySize, DSM_SEL);
    cudaFuncSetAttribute(nmsB_kernel,   cudaFuncAttributeMaxDynamicSharedMemorySize, DSM_B);

    cand_kernel  <<<dim3(5, BB, CH1), 256>>>(obj);
    select_kernel<<<dim3(5, BB), 512, DSM_SEL>>>(obj, deltas, anchors);
    nmsA_kernel  <<<dim3(5, BB, 16), 128>>>();
    nmsB_kernel  <<<dim3(5, BB), 512, DSM_B>>>();
    final_kernel <<<BB, 512>>>(out);
}